// round 1
// baseline (speedup 1.0000x reference)
#include <cuda_runtime.h>
#include <cstdint>
#include <cstddef>

#define HEADS 8
#define NTOK  64
#define DIMC  256
#define NWIN  2048
#define BNC   ((size_t)NWIN * NTOK * DIMC)   // 33,554,432

// ---------------- scratch (device globals; no allocation allowed) ----------
__device__ float g_bias[4 * HEADS * NTOK * NTOK];          // 512 KB
__device__ float g_att_v[(size_t)NWIN * NTOK * 512];       // 256 MB  [cross_v | self_v]
__device__ float g_att_h[(size_t)NWIN * NTOK * 512];       // 256 MB  [cross_h | self_h]

// ---------------- packed fp32x2 helpers (B300 dual-FP32 pipe) --------------
__device__ __forceinline__ unsigned long long splat2(float x) {
    unsigned long long r;
    asm("mov.b64 %0, {%1, %1};" : "=l"(r) : "r"(__float_as_uint(x)));
    return r;
}
__device__ __forceinline__ unsigned long long ffma2(unsigned long long a,
                                                    unsigned long long b,
                                                    unsigned long long c) {
    unsigned long long d;
    asm("fma.rn.f32x2 %0, %1, %2, %3;" : "=l"(d) : "l"(a), "l"(b), "l"(c));
    return d;
}
__device__ __forceinline__ void unpack2(unsigned long long v, float& lo, float& hi) {
    unsigned int a, b;
    asm("mov.b64 {%0, %1}, %2;" : "=r"(a), "=r"(b) : "l"(v));
    lo = __uint_as_float(a);
    hi = __uint_as_float(b);
}

// ---------------- kernel 0: relative-position bias gather ------------------
__global__ void bias_kernel(const float* __restrict__ tcv, const float* __restrict__ tsv,
                            const float* __restrict__ tch, const float* __restrict__ tsh,
                            const int* __restrict__ rpi) {
    int idx = blockIdx.x * blockDim.x + threadIdx.x;      // 4*8*64*64 = 131072
    if (idx >= 4 * HEADS * NTOK * NTOK) return;
    int m = idx & 63;
    int n = (idx >> 6) & 63;
    int h = (idx >> 12) & 7;
    int a = idx >> 15;
    const float* tab = (a == 0) ? tcv : (a == 1) ? tsv : (a == 2) ? tch : tsh;
    g_bias[idx] = tab[rpi[n * 64 + m] * HEADS + h];
}

// ---------------- kernel 1: fused per-window projections + attentions ------
// smem layout (floats):
//   XS  [64][256]                    16384
//   XE  [64][256]                    16384
//   QKV 8 tiles x [64][34]           17408   (pad 34: even -> 8B-aligned V pairs)
//   WC/SC union: WC[32][128] or SC[64][64]    4096
// total 54272 floats = 217,088 bytes
#define SMEM_FUSED_BYTES (54272 * 4)

__global__ __launch_bounds__(512, 1)
void fused_kernel(const float* __restrict__ input_x, const float* __restrict__ state_x,
                  const float* __restrict__ Ws, const float* __restrict__ bs,
                  const float* __restrict__ We, const float* __restrict__ be) {
    extern __shared__ float smf[];
    float* XS  = smf;
    float* XE  = smf + 16384;
    float* QKV = smf + 32768;
    float* WC  = smf + 32768 + 17408;   // union
    float* SC  = WC;                    // union

    const int b   = blockIdx.x;
    const int tid = threadIdx.x;
    const float kscale = 0.17677669529663687f;            // 32^-0.5

    // ---- load both x tiles (coalesced float4) ----
    {
        const float4* gs = (const float4*)(state_x + (size_t)b * (NTOK * DIMC));
        const float4* ge = (const float4*)(input_x + (size_t)b * (NTOK * DIMC));
        float4* xs4 = (float4*)XS;
        float4* xe4 = (float4*)XE;
        #pragma unroll
        for (int i = 0; i < 8; i++) {
            xs4[tid + i * 512] = gs[tid + i * 512];
            xe4[tid + i * 512] = ge[tid + i * 512];
        }
    }
    // (first __syncthreads inside the chunk loop orders these loads)

    const int rg = tid >> 5;   // 0..15 : 4-row group
    const int cg = tid & 31;   // 0..31 : 4-col group

    #pragma unroll 1
    for (int h = 0; h < HEADS; h++) {
        // ================= projections: two 64x256 @ 256x128 GEMMs =========
        #pragma unroll 1
        for (int src = 0; src < 2; src++) {
            const float* X  = src ? XE : XS;
            const float* W  = src ? We : Ws;
            const float* bv = src ? be : bs;

            // prefetch weight chunk 0 into registers
            float wreg[8];
            #pragma unroll
            for (int i = 0; i < 8; i++) {
                int e   = tid + i * 512;
                int cc  = e & 127;
                int col = ((cc >> 5) << 8) + (h << 5) + (cc & 31);
                wreg[i] = W[(size_t)(e >> 7) * 1024 + col];
            }

            unsigned long long acc[4][2];
            #pragma unroll
            for (int j = 0; j < 4; j++) { acc[j][0] = 0ull; acc[j][1] = 0ull; }

            #pragma unroll 1
            for (int kc = 0; kc < 256; kc += 32) {
                __syncthreads();                       // WC readers done
                #pragma unroll
                for (int i = 0; i < 8; i++) WC[tid + i * 512] = wreg[i];
                __syncthreads();                       // WC ready
                if (kc < 224) {                        // prefetch next chunk
                    #pragma unroll
                    for (int i = 0; i < 8; i++) {
                        int e   = tid + i * 512;
                        int cc  = e & 127;
                        int col = ((cc >> 5) << 8) + (h << 5) + (cc & 31);
                        wreg[i] = W[(size_t)(kc + 32 + (e >> 7)) * 1024 + col];
                    }
                }
                const float* Xr = X + kc;
                #pragma unroll
                for (int k = 0; k < 32; k++) {
                    const ulonglong2 b2 = *(const ulonglong2*)(WC + k * 128 + (cg << 2));
                    #pragma unroll
                    for (int j = 0; j < 4; j++) {
                        unsigned long long pa = splat2(Xr[(rg * 4 + j) * 256 + k]);
                        acc[j][0] = ffma2(pa, b2.x, acc[j][0]);
                        acc[j][1] = ffma2(pa, b2.y, acc[j][1]);
                    }
                }
            }

            // epilogue: +bias, scale per source/f, store to QKV tiles
            const float m2 = (src == 0) ? kscale : 1.0f;            // qsv / qev
            const float m3 = (src == 0) ? kscale * kscale : kscale; // qsh / qeh
            #pragma unroll
            for (int j = 0; j < 4; j++) {
                int n = rg * 4 + j;
                #pragma unroll
                for (int q = 0; q < 2; q++) {
                    float v0, v1;
                    unpack2(acc[j][q], v0, v1);
                    #pragma unroll
                    for (int t = 0; t < 2; t++) {
                        int c   = (cg << 2) + q * 2 + t;
                        int f   = c >> 5;
                        int d   = c & 31;
                        float v = (t ? v1 : v0) + bv[(f << 8) + (h << 5) + d];
                        if (f == 2) v *= m2;
                        if (f == 3) v *= m3;
                        QKV[((src * 4 + f) * 64 + n) * 34 + d] = v;
                    }
                }
            }
        }
        __syncthreads();   // QKV tiles complete for this head

        // ================= four attentions ================================
        // a0: qsv(2) ks(0) vs(1) -> att_v[0:256]   (cross_v)
        // a1: qev(6) ke(4) ve(5) -> att_v[256:512] (self_v)
        // a2: qeh(7) ke(4) ve(5) -> att_h[0:256]   (cross_h)
        // a3: qsh(3) ks(0) vs(1) -> att_h[256:512] (self_h)
        #pragma unroll 1
        for (int a = 0; a < 4; a++) {
            const int qt = (a == 0) ? 2 : (a == 1) ? 6 : (a == 2) ? 7 : 3;
            const int kt = (a == 0 || a == 3) ? 0 : 4;
            const float* Q  = QKV + qt * (64 * 34);
            const float* K  = QKV + kt * (64 * 34);
            const float* V  = QKV + (kt + 1) * (64 * 34);
            const float* Bp = g_bias + ((size_t)(a * HEADS + h) << 12);

            // ---- QK^T + bias + softmax : warp w owns rows w*4..w*4+3 ----
            const int w = tid >> 5, l = tid & 31;
            #pragma unroll
            for (int rp = 0; rp < 2; rp++) {
                int n0 = w * 4 + rp * 2;
                int n1 = n0 + 1;
                float s00 = Bp[n0 * 64 + l], s01 = Bp[n0 * 64 + l + 32];
                float s10 = Bp[n1 * 64 + l], s11 = Bp[n1 * 64 + l + 32];
                #pragma unroll
                for (int d = 0; d < 32; d++) {
                    float k0 = K[l * 34 + d];
                    float k1 = K[(l + 32) * 34 + d];
                    float q0 = Q[n0 * 34 + d];
                    float q1 = Q[n1 * 34 + d];
                    s00 += q0 * k0; s01 += q0 * k1;
                    s10 += q1 * k0; s11 += q1 * k1;
                }
                float mx0 = fmaxf(s00, s01), mx1 = fmaxf(s10, s11);
                #pragma unroll
                for (int o = 16; o; o >>= 1) {
                    mx0 = fmaxf(mx0, __shfl_xor_sync(0xffffffffu, mx0, o));
                    mx1 = fmaxf(mx1, __shfl_xor_sync(0xffffffffu, mx1, o));
                }
                float e00 = __expf(s00 - mx0), e01 = __expf(s01 - mx0);
                float e10 = __expf(s10 - mx1), e11 = __expf(s11 - mx1);
                float sum0 = e00 + e01, sum1 = e10 + e11;
                #pragma unroll
                for (int o = 16; o; o >>= 1) {
                    sum0 += __shfl_xor_sync(0xffffffffu, sum0, o);
                    sum1 += __shfl_xor_sync(0xffffffffu, sum1, o);
                }
                float inv0 = __fdividef(1.0f, sum0);
                float inv1 = __fdividef(1.0f, sum1);
                SC[n0 * 64 + l] = e00 * inv0; SC[n0 * 64 + l + 32] = e01 * inv0;
                SC[n1 * 64 + l] = e10 * inv1; SC[n1 * 64 + l + 32] = e11 * inv1;
            }
            __syncthreads();

            // ---- P @ V : thread owns (2 rows, 2 cols), packed fp32x2 -----
            const int ng = tid >> 4, dg = tid & 15;
            float* dstBuf = (a <= 1) ? g_att_v : g_att_h;
            const int colbase = ((a == 1 || a == 3) ? 256 : 0) + (h << 5) + (dg << 1);
            #pragma unroll
            for (int rr = 0; rr < 2; rr++) {
                int n = ng * 2 + rr;
                unsigned long long o2 = 0ull;
                const float* sp = SC + n * 64;
                #pragma unroll
                for (int m = 0; m < 64; m++) {
                    unsigned long long v2 =
                        *(const unsigned long long*)(V + m * 34 + (dg << 1));
                    o2 = ffma2(splat2(sp[m]), v2, o2);
                }
                float o0, o1;
                unpack2(o2, o0, o1);
                size_t addr = ((size_t)b * 64 + n) * 512 + colbase;
                dstBuf[addr]     = o0;
                dstBuf[addr + 1] = o1;
            }
            __syncthreads();   // protect SC before next attention / next head
        }
    }
}

// ---------------- kernel 2: output projection (131072x512)@(512x256) -------
__global__ __launch_bounds__(256, 2)
void proj_kernel(int which, const float* __restrict__ Wp,
                 const float* __restrict__ bp, float* __restrict__ out) {
    __shared__ __align__(16) float As[64 * 33];
    __shared__ __align__(16) float Bs[32 * 64];
    const float* A = which ? g_att_h : g_att_v;

    const int    tid = threadIdx.x;
    const size_t rb  = (size_t)blockIdx.x * 64;
    const int    cb  = blockIdx.y * 64;
    const int    rg  = tid >> 4, cgp = tid & 15;

    unsigned long long acc[4][2];
    #pragma unroll
    for (int j = 0; j < 4; j++) { acc[j][0] = 0ull; acc[j][1] = 0ull; }

    #pragma unroll 1
    for (int kc = 0; kc < 512; kc += 32) {
        __syncthreads();
        #pragma unroll
        for (int i = 0; i < 2; i++) {
            int e4 = tid + i * 256;                 // 512 float4 of A chunk
            int r  = e4 >> 3;
            int k4 = (e4 & 7) << 2;
            float4 va = *(const float4*)(A + (rb + r) * 512 + kc + k4);
            float* dp = As + r * 33 + k4;
            dp[0] = va.x; dp[1] = va.y; dp[2] = va.z; dp[3] = va.w;
        }
        #pragma unroll
        for (int i = 0; i < 2; i++) {
            int e4 = tid + i * 256;                 // 512 float4 of B chunk
            int k  = e4 >> 4;
            int c4 = (e4 & 15) << 2;
            *(float4*)(Bs + k * 64 + c4) =
                *(const float4*)(Wp + (size_t)(kc + k) * 256 + cb + c4);
        }
        __syncthreads();
        #pragma unroll
        for (int k = 0; k < 32; k++) {
            const ulonglong2 b2 = *(const ulonglong2*)(Bs + k * 64 + (cgp << 2));
            #pragma unroll
            for (int j = 0; j < 4; j++) {
                unsigned long long pa = splat2(As[(rg * 4 + j) * 33 + k]);
                acc[j][0] = ffma2(pa, b2.x, acc[j][0]);
                acc[j][1] = ffma2(pa, b2.y, acc[j][1]);
            }
        }
    }

    const int c0 = cb + (cgp << 2);
    const float4 bias4 = *(const float4*)(bp + c0);
    #pragma unroll
    for (int j = 0; j < 4; j++) {
        float v0, v1, v2, v3;
        unpack2(acc[j][0], v0, v1);
        unpack2(acc[j][1], v2, v3);
        float4 r = make_float4(v0 + bias4.x, v1 + bias4.y, v2 + bias4.z, v3 + bias4.w);
        *(float4*)(out + (rb + rg * 4 + j) * 256 + c0) = r;
    }
}

// ---------------- launch ----------------------------------------------------
extern "C" void kernel_launch(void* const* d_in, const int* in_sizes, int n_in,
                              void* d_out, int out_size) {
    const float* input_x = (const float*)d_in[0];
    const float* state_x = (const float*)d_in[1];
    const float* Ws  = (const float*)d_in[2];
    const float* bs  = (const float*)d_in[3];
    const float* We  = (const float*)d_in[4];
    const float* be  = (const float*)d_in[5];
    const float* Wpv = (const float*)d_in[6];
    const float* bpv = (const float*)d_in[7];
    const float* Wph = (const float*)d_in[8];
    const float* bph = (const float*)d_in[9];
    const float* tcv = (const float*)d_in[10];
    const float* tsv = (const float*)d_in[11];
    const float* tch = (const float*)d_in[12];
    const float* tsh = (const float*)d_in[13];
    const int*   rpi = (const int*)d_in[14];
    float* out = (float*)d_out;

    cudaFuncSetAttribute(fused_kernel, cudaFuncAttributeMaxDynamicSharedMemorySize,
                         SMEM_FUSED_BYTES);

    bias_kernel<<<512, 256>>>(tcv, tsv, tch, tsh, rpi);
    fused_kernel<<<NWIN, 512, SMEM_FUSED_BYTES>>>(input_x, state_x, Ws, bs, We, be);

    dim3 pgrid(NWIN, 4);   // 2048 row-blocks x 4 col-blocks
    proj_kernel<<<pgrid, 256>>>(0, Wpv, bpv, out);
    proj_kernel<<<pgrid, 256>>>(1, Wph, bph, out + BNC);
}

// round 3
// speedup vs baseline: 2.4376x; 2.4376x over previous
#include <cuda_runtime.h>
#include <cuda_fp16.h>
#include <cstdint>
#include <cstddef>

#define HEADS 8
#define NWIN  2048
#define MROWS (NWIN * 64)                   // 131072 token rows
#define BNC   ((size_t)MROWS * 256)         // 33,554,432 output elems per tensor

// ---------------- scratch (device globals; no allocation allowed) ----------
__device__ __half g_xh[2][(size_t)MROWS * 256];     // 134 MB  fp16 inputs (0=state,1=input)
__device__ __half g_wt[2][1024 * 256];              // 1 MB    QKV weights, [src][col][k]
__device__ __half g_wpt[2][256 * 512];              // 0.5 MB  out-proj weights, [w][n][k]
__device__ __half g_qkv[(size_t)NWIN * 2 * 4 * HEADS * 64 * 32];  // 512 MB head tiles
__device__ __half g_attv[(size_t)MROWS * 512];      // 134 MB  [cross_v | self_v]
__device__ __half g_atth[(size_t)MROWS * 512];      // 134 MB  [cross_h | self_h]
__device__ float  g_bias[4 * HEADS * 64 * 64];      // 512 KB

// ---------------- helpers ---------------------------------------------------
__device__ __forceinline__ uint32_t smem_u32(const void* p) {
    uint32_t a;
    asm("{ .reg .u64 t; cvta.to.shared.u64 t, %1; cvt.u32.u64 %0, t; }" : "=r"(a) : "l"(p));
    return a;
}
#define CP_ASYNC16(dst, src) \
    asm volatile("cp.async.cg.shared.global [%0], [%1], 16;" :: "r"(dst), "l"(src))
#define CP_COMMIT() asm volatile("cp.async.commit_group;" ::: "memory")

#define LDSM_X4(r, addr) \
    asm volatile("ldmatrix.sync.aligned.m8n8.x4.shared.b16 {%0,%1,%2,%3}, [%4];" \
        : "=r"((r)[0]), "=r"((r)[1]), "=r"((r)[2]), "=r"((r)[3]) : "r"(addr))

#define MMA_16816(c, a, b0, b1) \
    asm volatile("mma.sync.aligned.m16n8k16.row.col.f32.f16.f16.f32 " \
        "{%0,%1,%2,%3}, {%4,%5,%6,%7}, {%8,%9}, {%0,%1,%2,%3};" \
        : "+f"((c)[0]), "+f"((c)[1]), "+f"((c)[2]), "+f"((c)[3]) \
        : "r"((a)[0]), "r"((a)[1]), "r"((a)[2]), "r"((a)[3]), "r"(b0), "r"(b1))

// packed fp32x2 (dual-FP32 pipe) for the scalar attention PV stage
__device__ __forceinline__ unsigned long long splat2(float x) {
    unsigned long long r;
    asm("mov.b64 %0, {%1, %1};" : "=l"(r) : "r"(__float_as_uint(x)));
    return r;
}
__device__ __forceinline__ unsigned long long ffma2(unsigned long long a,
                                                    unsigned long long b,
                                                    unsigned long long c) {
    unsigned long long d;
    asm("fma.rn.f32x2 %0, %1, %2, %3;" : "=l"(d) : "l"(a), "l"(b), "l"(c));
    return d;
}
__device__ __forceinline__ void unpack2(unsigned long long v, float& lo, float& hi) {
    unsigned int a, b;
    asm("mov.b64 {%0, %1}, %2;" : "=r"(a), "=r"(b) : "l"(v));
    lo = __uint_as_float(a); hi = __uint_as_float(b);
}

// ---------------- prep kernels ----------------------------------------------
__global__ void bias_kernel(const float* __restrict__ tcv, const float* __restrict__ tsv,
                            const float* __restrict__ tch, const float* __restrict__ tsh,
                            const int* __restrict__ rpi) {
    int idx = blockIdx.x * blockDim.x + threadIdx.x;   // 131072
    if (idx >= 4 * HEADS * 64 * 64) return;
    int m = idx & 63, n = (idx >> 6) & 63, h = (idx >> 12) & 7, a = idx >> 15;
    const float* tab = (a == 0) ? tcv : (a == 1) ? tsv : (a == 2) ? tch : tsh;
    g_bias[idx] = tab[rpi[n * 64 + m] * HEADS + h];
}

__global__ void xprep_kernel(const float* __restrict__ input_x,
                             const float* __restrict__ state_x) {
    int src = blockIdx.y;
    const float4* X = (const float4*)(src ? input_x : state_x);
    size_t t = (size_t)blockIdx.x * 256 + threadIdx.x;          // 4,194,304 per src
    float4 v0 = X[t * 2], v1 = X[t * 2 + 1];
    __half2 h0 = __floats2half2_rn(v0.x, v0.y), h1 = __floats2half2_rn(v0.z, v0.w);
    __half2 h2 = __floats2half2_rn(v1.x, v1.y), h3 = __floats2half2_rn(v1.z, v1.w);
    uint4 u;
    u.x = *(uint32_t*)&h0; u.y = *(uint32_t*)&h1;
    u.z = *(uint32_t*)&h2; u.w = *(uint32_t*)&h3;
    ((uint4*)g_xh[src])[t] = u;
}

__global__ void wprep_kernel(const float* __restrict__ Ws, const float* __restrict__ We) {
    int idx = blockIdx.x * 256 + threadIdx.x;          // 524288
    int k = idx & 255, c = (idx >> 8) & 1023, src = idx >> 18;
    const float* W = src ? We : Ws;
    g_wt[src][c * 256 + k] = __float2half_rn(W[(size_t)k * 1024 + c]);
}
__global__ void wpprep_kernel(const float* __restrict__ Wpv, const float* __restrict__ Wph) {
    int idx = blockIdx.x * 256 + threadIdx.x;          // 262144
    int k = idx & 511, n = (idx >> 9) & 255, w = idx >> 17;
    const float* W = w ? Wph : Wpv;
    g_wpt[w][n * 512 + k] = __float2half_rn(W[(size_t)k * 256 + n]);
}

// ---------------- HMMA GEMM core: 128x64 CTA tile, 8 warps, 2-stage cp.async
template<int KT>
__device__ __forceinline__ void hgemm_core(const __half* __restrict__ A,
                                           const __half* __restrict__ B,
                                           int mb, int nb,
                                           __half* SA, __half* SB,
                                           float acc[2][4][4]) {
    const int tid = threadIdx.x, w = tid >> 5, lane = tid & 31;
    const int wm = (w >> 1) * 32, wn = (w & 1) * 32;
    #pragma unroll
    for (int t = 0; t < 2; t++)
        #pragma unroll
        for (int j = 0; j < 4; j++)
            #pragma unroll
            for (int r = 0; r < 4; r++) acc[t][j][r] = 0.0f;

    const int KC = KT / 64;
    auto issue = [&](int s, int kc) {
        __half* sa = SA + s * (128 * 64);
        __half* sb = SB + s * (64 * 64);
        #pragma unroll
        for (int i = 0; i < 4; i++) {
            int ch = tid + i * 256, r = ch >> 3, k8 = ch & 7;
            uint32_t d = smem_u32(sa + r * 64 + ((k8 ^ (r & 7)) << 3));
            CP_ASYNC16(d, A + (size_t)(mb * 128 + r) * KT + kc * 64 + k8 * 8);
        }
        #pragma unroll
        for (int i = 0; i < 2; i++) {
            int ch = tid + i * 256, r = ch >> 3, k8 = ch & 7;
            uint32_t d = smem_u32(sb + r * 64 + ((k8 ^ (r & 7)) << 3));
            CP_ASYNC16(d, B + (size_t)(nb * 64 + r) * KT + kc * 64 + k8 * 8);
        }
    };
    issue(0, 0);
    CP_COMMIT();

    #pragma unroll 1
    for (int kc = 0; kc < KC; kc++) {
        int s = kc & 1;
        if (kc + 1 < KC) {
            issue(s ^ 1, kc + 1);
            CP_COMMIT();
            asm volatile("cp.async.wait_group 1;" ::: "memory");
        } else {
            asm volatile("cp.async.wait_group 0;" ::: "memory");
        }
        __syncthreads();

        uint32_t baseA = smem_u32(SA + s * (128 * 64));
        uint32_t baseB = smem_u32(SB + s * (64 * 64));
        #pragma unroll
        for (int ks = 0; ks < 4; ks++) {
            uint32_t af[2][4], bf[2][4];
            #pragma unroll
            for (int t = 0; t < 2; t++) {
                int row = wm + t * 16 + (lane & 15);
                int kc8 = ks * 2 + (lane >> 4);
                uint32_t ad = baseA + ((row * 64 + ((kc8 ^ (row & 7)) << 3)) << 1);
                LDSM_X4(af[t], ad);
            }
            #pragma unroll
            for (int p = 0; p < 2; p++) {
                int n   = wn + p * 16 + ((lane >> 4) << 3) + (lane & 7);
                int kc8 = ks * 2 + ((lane >> 3) & 1);
                uint32_t bd = baseB + ((n * 64 + ((kc8 ^ (n & 7)) << 3)) << 1);
                LDSM_X4(bf[p], bd);
            }
            #pragma unroll
            for (int t = 0; t < 2; t++)
                #pragma unroll
                for (int j = 0; j < 4; j++)
                    MMA_16816(acc[t][j], af[t],
                              bf[j >> 1][(j & 1) * 2], bf[j >> 1][(j & 1) * 2 + 1]);
        }
        __syncthreads();
    }
}

// ---------------- QKV projection GEMM ---------------------------------------
// grid (1024 m-blocks, 16 n-blocks, 2 src); X[131072,256]fp16 @ Wt[1024,256]^T
__global__ __launch_bounds__(256)
void qkv_gemm(const float* __restrict__ bs, const float* __restrict__ be) {
    __shared__ __align__(16) __half SA[2 * 128 * 64];
    __shared__ __align__(16) __half SB[2 * 64 * 64];
    const int mb = blockIdx.x, nb = blockIdx.y, src = blockIdx.z;

    float acc[2][4][4];
    hgemm_core<256>(g_xh[src], g_wt[src], mb, nb, SA, SB, acc);

    const float* bv = src ? be : bs;
    const float kscale = 0.17677669529663687f;
    const float m2 = src ? 1.0f : kscale;                // qsv / qev
    const float m3 = src ? kscale : kscale * kscale;     // qsh / qeh

    const int tid = threadIdx.x, w = tid >> 5, lane = tid & 31;
    const int wm = (w >> 1) * 32, wn = (w & 1) * 32;
    const int gid = lane >> 2, tig = lane & 3;

    #pragma unroll
    for (int t = 0; t < 2; t++)
        #pragma unroll
        for (int j = 0; j < 4; j++) {
            int nglob = nb * 64 + wn + j * 8 + tig * 2;   // 0..1023
            int f = nglob >> 8, h = (nglob >> 5) & 7, d = nglob & 31;
            float mult = (f == 2) ? m2 : (f == 3) ? m3 : 1.0f;
            float b0 = bv[nglob], b1 = bv[nglob + 1];
            #pragma unroll
            for (int rr = 0; rr < 2; rr++) {
                int m = mb * 128 + wm + t * 16 + gid + rr * 8;
                int b = m >> 6, ntok = m & 63;
                size_t tile = ((((size_t)b * 2 + src) * 4 + f) * 8 + h) * 2048;
                __half2 hv = __floats2half2_rn((acc[t][j][rr * 2]     + b0) * mult,
                                               (acc[t][j][rr * 2 + 1] + b1) * mult);
                *(__half2*)(g_qkv + tile + ntok * 32 + d) = hv;
            }
        }
}

// ---------------- attention kernel (scalar, per window) ---------------------
#define SM_A ((17408 + 4096) * 4)

__global__ __launch_bounds__(512, 2)
void attn_kernel() {
    extern __shared__ float smf[];
    float* QKV = smf;           // 8 tiles [64][34]
    float* SC  = smf + 17408;   // [64][64]
    const int b = blockIdx.x, tid = threadIdx.x;
    const uint32_t* qkv_u = (const uint32_t*)g_qkv;

    #pragma unroll 1
    for (int h = 0; h < HEADS; h++) {
        #pragma unroll 4
        for (int i = 0; i < 16; i++) {
            int e = tid + i * 512;                 // 8192 uints
            int t = e >> 10, r = e & 1023;
            int srcS = t >> 2, f = t & 3;
            size_t tile = (size_t)(((b * 2 + srcS) * 4 + f) * 8 + h) * 1024;
            uint32_t u = qkv_u[tile + r];
            float2 fv = __half22float2(*(__half2*)&u);
            int n = r >> 4, d2 = r & 15;
            *(float2*)(QKV + t * 2176 + n * 34 + d2 * 2) = fv;
        }
        __syncthreads();

        #pragma unroll 1
        for (int a = 0; a < 4; a++) {
            const int qt = (a == 0) ? 2 : (a == 1) ? 6 : (a == 2) ? 7 : 3;
            const int kt = (a == 0 || a == 3) ? 0 : 4;
            const float* Q = QKV + qt * 2176;
            const float* K = QKV + kt * 2176;
            const float* V = QKV + (kt + 1) * 2176;
            const float* Bp = g_bias + ((size_t)(a * HEADS + h) << 12);

            const int w = tid >> 5, l = tid & 31;
            #pragma unroll
            for (int rp = 0; rp < 2; rp++) {
                int n0 = w * 4 + rp * 2, n1 = n0 + 1;
                float s00 = Bp[n0 * 64 + l], s01 = Bp[n0 * 64 + l + 32];
                float s10 = Bp[n1 * 64 + l], s11 = Bp[n1 * 64 + l + 32];
                #pragma unroll
                for (int d = 0; d < 32; d++) {
                    float k0 = K[l * 34 + d], k1 = K[(l + 32) * 34 + d];
                    float q0 = Q[n0 * 34 + d], q1 = Q[n1 * 34 + d];
                    s00 += q0 * k0; s01 += q0 * k1;
                    s10 += q1 * k0; s11 += q1 * k1;
                }
                float mx0 = fmaxf(s00, s01), mx1 = fmaxf(s10, s11);
                #pragma unroll
                for (int o = 16; o; o >>= 1) {
                    mx0 = fmaxf(mx0, __shfl_xor_sync(0xffffffffu, mx0, o));
                    mx1 = fmaxf(mx1, __shfl_xor_sync(0xffffffffu, mx1, o));
                }
                float e00 = __expf(s00 - mx0), e01 = __expf(s01 - mx0);
                float e10 = __expf(s10 - mx1), e11 = __expf(s11 - mx1);
                float sum0 = e00 + e01, sum1 = e10 + e11;
                #pragma unroll
                for (int o = 16; o; o >>= 1) {
                    sum0 += __shfl_xor_sync(0xffffffffu, sum0, o);
                    sum1 += __shfl_xor_sync(0xffffffffu, sum1, o);
                }
                float inv0 = __fdividef(1.0f, sum0), inv1 = __fdividef(1.0f, sum1);
                SC[n0 * 64 + l] = e00 * inv0; SC[n0 * 64 + l + 32] = e01 * inv0;
                SC[n1 * 64 + l] = e10 * inv1; SC[n1 * 64 + l + 32] = e11 * inv1;
            }
            __syncthreads();

            const int ng = tid >> 4, dg = tid & 15;
            __half* dst = (a <= 1) ? g_attv : g_atth;
            const int colbase = ((a == 1 || a == 3) ? 256 : 0) + (h << 5) + (dg << 1);
            #pragma unroll
            for (int rr = 0; rr < 2; rr++) {
                int n = ng * 2 + rr;
                unsigned long long o2 = 0ull;
                const float* sp = SC + n * 64;
                #pragma unroll
                for (int m = 0; m < 64; m++) {
                    unsigned long long v2 =
                        *(const unsigned long long*)(V + m * 34 + (dg << 1));
                    o2 = ffma2(splat2(sp[m]), v2, o2);
                }
                float o0, o1; unpack2(o2, o0, o1);
                *(__half2*)(dst + ((size_t)(b * 64 + n) * 512 + colbase)) =
                    __floats2half2_rn(o0, o1);
            }
            __syncthreads();
        }
    }
}

// ---------------- output projection GEMM ------------------------------------
// grid (1024 m-blocks, 4 n-blocks); A[131072,512]fp16 @ Wpt[256,512]^T -> fp32
__global__ __launch_bounds__(256)
void out_gemm(int which, const float* __restrict__ bp, float* __restrict__ out) {
    __shared__ __align__(16) __half SA[2 * 128 * 64];
    __shared__ __align__(16) __half SB[2 * 64 * 64];
    const int mb = blockIdx.x, nb = blockIdx.y;
    const __half* A = which ? g_atth : g_attv;

    float acc[2][4][4];
    hgemm_core<512>(A, g_wpt[which], mb, nb, SA, SB, acc);

    const int tid = threadIdx.x, w = tid >> 5, lane = tid & 31;
    const int wm = (w >> 1) * 32, wn = (w & 1) * 32;
    const int gid = lane >> 2, tig = lane & 3;

    #pragma unroll
    for (int t = 0; t < 2; t++)
        #pragma unroll
        for (int j = 0; j < 4; j++) {
            int n = nb * 64 + wn + j * 8 + tig * 2;       // 0..255
            float b0 = bp[n], b1 = bp[n + 1];
            #pragma unroll
            for (int rr = 0; rr < 2; rr++) {
                int m = mb * 128 + wm + t * 16 + gid + rr * 8;
                float2 v = make_float2(acc[t][j][rr * 2] + b0,
                                       acc[t][j][rr * 2 + 1] + b1);
                *(float2*)(out + (size_t)m * 256 + n) = v;
            }
        }
}

// ---------------- launch -----------------------------------------------------
extern "C" void kernel_launch(void* const* d_in, const int* in_sizes, int n_in,
                              void* d_out, int out_size) {
    const float* input_x = (const float*)d_in[0];
    const float* state_x = (const float*)d_in[1];
    const float* Ws  = (const float*)d_in[2];
    const float* bs  = (const float*)d_in[3];
    const float* We  = (const float*)d_in[4];
    const float* be  = (const float*)d_in[5];
    const float* Wpv = (const float*)d_in[6];
    const float* bpv = (const float*)d_in[7];
    const float* Wph = (const float*)d_in[8];
    const float* bph = (const float*)d_in[9];
    const float* tcv = (const float*)d_in[10];
    const float* tsv = (const float*)d_in[11];
    const float* tch = (const float*)d_in[12];
    const float* tsh = (const float*)d_in[13];
    const int*   rpi = (const int*)d_in[14];
    float* out = (float*)d_out;

    cudaFuncSetAttribute(attn_kernel, cudaFuncAttributeMaxDynamicSharedMemorySize, SM_A);

    bias_kernel<<<512, 256>>>(tcv, tsv, tch, tsh, rpi);
    xprep_kernel<<<dim3(16384, 2), 256>>>(input_x, state_x);
    wprep_kernel<<<2048, 256>>>(Ws, We);
    wpprep_kernel<<<1024, 256>>>(Wpv, Wph);

    qkv_gemm<<<dim3(1024, 16, 2), 256>>>(bs, be);
    attn_kernel<<<NWIN, 512, SM_A>>>();
    out_gemm<<<dim3(1024, 4), 256>>>(0, bpv, out);
    out_gemm<<<dim3(1024, 4), 256>>>(1, bph, out + BNC);
}

// round 4
// speedup vs baseline: 5.9498x; 2.4409x over previous
#include <cuda_runtime.h>
#include <cuda_fp16.h>
#include <cstdint>
#include <cstddef>

#define HEADS 8
#define NWIN  2048
#define MROWS (NWIN * 64)                   // 131072 token rows
#define BNC   ((size_t)MROWS * 256)         // 33,554,432 output elems per tensor

// ---------------- scratch (device globals; no allocation allowed) ----------
__device__ __half g_xh[2][(size_t)MROWS * 256];     // fp16 inputs (0=state,1=input)
__device__ __half g_wt[2][1024 * 256];              // QKV weights, [src][col][k]
__device__ __half g_wpt[2][256 * 512];              // out-proj weights, [w][n][k]
__device__ __half g_qkv[(size_t)NWIN * 2 * 4 * HEADS * 64 * 32];  // head tiles
__device__ __half g_attv[(size_t)MROWS * 512];      // [cross_v | self_v]
__device__ __half g_atth[(size_t)MROWS * 512];      // [cross_h | self_h]
__device__ float  g_bias[4 * HEADS * 64 * 64];      // 512 KB

// ---------------- helpers ---------------------------------------------------
__device__ __forceinline__ uint32_t smem_u32(const void* p) {
    uint32_t a;
    asm("{ .reg .u64 t; cvta.to.shared.u64 t, %1; cvt.u32.u64 %0, t; }" : "=r"(a) : "l"(p));
    return a;
}
#define CP_ASYNC16(dst, src) \
    asm volatile("cp.async.cg.shared.global [%0], [%1], 16;" :: "r"(dst), "l"(src))
#define CP_COMMIT() asm volatile("cp.async.commit_group;" ::: "memory")

#define LDSM_X4(r, addr) \
    asm volatile("ldmatrix.sync.aligned.m8n8.x4.shared.b16 {%0,%1,%2,%3}, [%4];" \
        : "=r"((r)[0]), "=r"((r)[1]), "=r"((r)[2]), "=r"((r)[3]) : "r"(addr))

#define MMA_16816(c, a, b0, b1) \
    asm volatile("mma.sync.aligned.m16n8k16.row.col.f32.f16.f16.f32 " \
        "{%0,%1,%2,%3}, {%4,%5,%6,%7}, {%8,%9}, {%0,%1,%2,%3};" \
        : "+f"((c)[0]), "+f"((c)[1]), "+f"((c)[2]), "+f"((c)[3]) \
        : "r"((a)[0]), "r"((a)[1]), "r"((a)[2]), "r"((a)[3]), "r"(b0), "r"(b1))

// split a float pair into fp16 high + fp16 low (residual) packs
__device__ __forceinline__ void pack_hl(float x, float y, uint32_t& hi, uint32_t& lo) {
    __half2 h = __floats2half2_rn(x, y);
    float2 r = __half22float2(h);
    __half2 l = __floats2half2_rn(x - r.x, y - r.y);
    hi = *(uint32_t*)&h;
    lo = *(uint32_t*)&l;
}

// ---------------- prep kernels ----------------------------------------------
__global__ void bias_kernel(const float* __restrict__ tcv, const float* __restrict__ tsv,
                            const float* __restrict__ tch, const float* __restrict__ tsh,
                            const int* __restrict__ rpi) {
    int idx = blockIdx.x * blockDim.x + threadIdx.x;   // 131072
    if (idx >= 4 * HEADS * 64 * 64) return;
    int m = idx & 63, n = (idx >> 6) & 63, h = (idx >> 12) & 7, a = idx >> 15;
    const float* tab = (a == 0) ? tcv : (a == 1) ? tsv : (a == 2) ? tch : tsh;
    g_bias[idx] = tab[rpi[n * 64 + m] * HEADS + h];
}

__global__ void xprep_kernel(const float* __restrict__ input_x,
                             const float* __restrict__ state_x) {
    int src = blockIdx.y;
    const float4* X = (const float4*)(src ? input_x : state_x);
    size_t t = (size_t)blockIdx.x * 256 + threadIdx.x;
    float4 v0 = X[t * 2], v1 = X[t * 2 + 1];
    __half2 h0 = __floats2half2_rn(v0.x, v0.y), h1 = __floats2half2_rn(v0.z, v0.w);
    __half2 h2 = __floats2half2_rn(v1.x, v1.y), h3 = __floats2half2_rn(v1.z, v1.w);
    uint4 u;
    u.x = *(uint32_t*)&h0; u.y = *(uint32_t*)&h1;
    u.z = *(uint32_t*)&h2; u.w = *(uint32_t*)&h3;
    ((uint4*)g_xh[src])[t] = u;
}

__global__ void wprep_kernel(const float* __restrict__ Ws, const float* __restrict__ We) {
    int idx = blockIdx.x * 256 + threadIdx.x;          // 524288
    int k = idx & 255, c = (idx >> 8) & 1023, src = idx >> 18;
    const float* W = src ? We : Ws;
    g_wt[src][c * 256 + k] = __float2half_rn(W[(size_t)k * 1024 + c]);
}
__global__ void wpprep_kernel(const float* __restrict__ Wpv, const float* __restrict__ Wph) {
    int idx = blockIdx.x * 256 + threadIdx.x;          // 262144
    int k = idx & 511, n = (idx >> 9) & 255, w = idx >> 17;
    const float* W = w ? Wph : Wpv;
    g_wpt[w][n * 512 + k] = __float2half_rn(W[(size_t)k * 256 + n]);
}

// ---------------- HMMA GEMM core: 128x64 CTA tile, 8 warps, 2-stage cp.async
template<int KT>
__device__ __forceinline__ void hgemm_core(const __half* __restrict__ A,
                                           const __half* __restrict__ B,
                                           int mb, int nb,
                                           __half* SA, __half* SB,
                                           float acc[2][4][4]) {
    const int tid = threadIdx.x, w = tid >> 5, lane = tid & 31;
    const int wm = (w >> 1) * 32, wn = (w & 1) * 32;
    #pragma unroll
    for (int t = 0; t < 2; t++)
        #pragma unroll
        for (int j = 0; j < 4; j++)
            #pragma unroll
            for (int r = 0; r < 4; r++) acc[t][j][r] = 0.0f;

    const int KC = KT / 64;
    auto issue = [&](int s, int kc) {
        __half* sa = SA + s * (128 * 64);
        __half* sb = SB + s * (64 * 64);
        #pragma unroll
        for (int i = 0; i < 4; i++) {
            int ch = tid + i * 256, r = ch >> 3, k8 = ch & 7;
            uint32_t d = smem_u32(sa + r * 64 + ((k8 ^ (r & 7)) << 3));
            CP_ASYNC16(d, A + (size_t)(mb * 128 + r) * KT + kc * 64 + k8 * 8);
        }
        #pragma unroll
        for (int i = 0; i < 2; i++) {
            int ch = tid + i * 256, r = ch >> 3, k8 = ch & 7;
            uint32_t d = smem_u32(sb + r * 64 + ((k8 ^ (r & 7)) << 3));
            CP_ASYNC16(d, B + (size_t)(nb * 64 + r) * KT + kc * 64 + k8 * 8);
        }
    };
    issue(0, 0);
    CP_COMMIT();

    #pragma unroll 1
    for (int kc = 0; kc < KC; kc++) {
        int s = kc & 1;
        if (kc + 1 < KC) {
            issue(s ^ 1, kc + 1);
            CP_COMMIT();
            asm volatile("cp.async.wait_group 1;" ::: "memory");
        } else {
            asm volatile("cp.async.wait_group 0;" ::: "memory");
        }
        __syncthreads();

        uint32_t baseA = smem_u32(SA + s * (128 * 64));
        uint32_t baseB = smem_u32(SB + s * (64 * 64));
        #pragma unroll
        for (int ks = 0; ks < 4; ks++) {
            uint32_t af[2][4], bf[2][4];
            #pragma unroll
            for (int t = 0; t < 2; t++) {
                int row = wm + t * 16 + (lane & 15);
                int kc8 = ks * 2 + (lane >> 4);
                uint32_t ad = baseA + ((row * 64 + ((kc8 ^ (row & 7)) << 3)) << 1);
                LDSM_X4(af[t], ad);
            }
            #pragma unroll
            for (int p = 0; p < 2; p++) {
                int n   = wn + p * 16 + ((lane >> 4) << 3) + (lane & 7);
                int kc8 = ks * 2 + ((lane >> 3) & 1);
                uint32_t bd = baseB + ((n * 64 + ((kc8 ^ (n & 7)) << 3)) << 1);
                LDSM_X4(bf[p], bd);
            }
            #pragma unroll
            for (int t = 0; t < 2; t++)
                #pragma unroll
                for (int j = 0; j < 4; j++)
                    MMA_16816(acc[t][j], af[t],
                              bf[j >> 1][(j & 1) * 2], bf[j >> 1][(j & 1) * 2 + 1]);
        }
        __syncthreads();
    }
}

// ---------------- QKV projection GEMM ---------------------------------------
__global__ __launch_bounds__(256)
void qkv_gemm(const float* __restrict__ bs, const float* __restrict__ be) {
    __shared__ __align__(16) __half SA[2 * 128 * 64];
    __shared__ __align__(16) __half SB[2 * 64 * 64];
    const int mb = blockIdx.x, nb = blockIdx.y, src = blockIdx.z;

    float acc[2][4][4];
    hgemm_core<256>(g_xh[src], g_wt[src], mb, nb, SA, SB, acc);

    const float* bv = src ? be : bs;
    const float kscale = 0.17677669529663687f;
    const float m2 = src ? 1.0f : kscale;                // qsv / qev
    const float m3 = src ? kscale : kscale * kscale;     // qsh / qeh

    const int tid = threadIdx.x, w = tid >> 5, lane = tid & 31;
    const int wm = (w >> 1) * 32, wn = (w & 1) * 32;
    const int gid = lane >> 2, tig = lane & 3;

    #pragma unroll
    for (int t = 0; t < 2; t++)
        #pragma unroll
        for (int j = 0; j < 4; j++) {
            int nglob = nb * 64 + wn + j * 8 + tig * 2;   // 0..1023
            int f = nglob >> 8, h = (nglob >> 5) & 7, d = nglob & 31;
            float mult = (f == 2) ? m2 : (f == 3) ? m3 : 1.0f;
            float b0 = bv[nglob], b1 = bv[nglob + 1];
            #pragma unroll
            for (int rr = 0; rr < 2; rr++) {
                int m = mb * 128 + wm + t * 16 + gid + rr * 8;
                int b = m >> 6, ntok = m & 63;
                size_t tile = ((((size_t)b * 2 + src) * 4 + f) * 8 + h) * 2048;
                float v0 = (acc[t][j][rr * 2] + b0) * mult;
                float v1 = (acc[t][j][rr * 2 + 1] + b1) * mult;
                if (f == 1) {
                    // V stored transposed: [d][tok] rows of 64 tokens
                    g_qkv[tile + (size_t)d * 64 + ntok]       = __float2half_rn(v0);
                    g_qkv[tile + (size_t)(d + 1) * 64 + ntok] = __float2half_rn(v1);
                } else {
                    __half2 hv = __floats2half2_rn(v0, v1);
                    *(__half2*)(g_qkv + tile + ntok * 32 + d) = hv;
                }
            }
        }
}

// ---------------- attention kernel (HMMA flash-style) -----------------------
// CTA = 1 window, 8 warps = 4 attentions x 2 row-halves, loop 8 heads.
// smem: 2 stages x 8 tiles x 4KB = 64KB (dynamic).
#define SM_ATT (2 * 8 * 2048 * 2)

__global__ __launch_bounds__(256, 2)
void attn_kernel() {
    extern __shared__ __half smh[];
    const int b = blockIdx.x, tid = threadIdx.x;
    const int w = tid >> 5, lane = tid & 31;
    const int gid = lane >> 2, tig = lane & 3;
    const int a = w >> 1, hf = w & 1;

    const int qt = (a == 0) ? 2 : (a == 1) ? 6 : (a == 2) ? 7 : 3;
    const int kt = (a == 0 || a == 3) ? 0 : 4;
    const int vt = kt + 1;
    __half* dst0 = (a <= 1) ? g_attv : g_atth;
    const int cbase = (a == 1 || a == 3) ? 256 : 0;

    // stage head h's 8 tiles into buffer st via cp.async (all threads)
    auto stage = [&](int st, int h) {
        #pragma unroll
        for (int i = 0; i < 8; i++) {
            int ch = tid + i * 256;             // 2048 chunks of 16B
            int t = ch >> 8, c = ch & 255;
            const __half* src = g_qkv +
                ((((size_t)b * 2 + (t >> 2)) * 4 + (t & 3)) * 8 + h) * 2048 + c * 8;
            uint32_t off;
            if ((t & 3) == 1) {                 // V^T tile [32][64]
                int r = c >> 3, c8 = c & 7;
                off = r * 64 + ((c8 ^ (r & 7)) << 3);
            } else {                            // Q/K tile [64][32]
                int r = c >> 2, c4 = c & 3;
                off = r * 32 + ((c4 ^ ((r >> 1) & 3)) << 3);
            }
            CP_ASYNC16(smem_u32(smh + (st * 8 + t) * 2048 + off), src);
        }
    };

    stage(0, 0);
    CP_COMMIT();

    #pragma unroll 1
    for (int h = 0; h < HEADS; h++) {
        int st = h & 1;
        if (h < 7) {
            stage(st ^ 1, h + 1);
            CP_COMMIT();
            asm volatile("cp.async.wait_group 1;" ::: "memory");
        } else {
            asm volatile("cp.async.wait_group 0;" ::: "memory");
        }
        __syncthreads();

        uint32_t Qb = smem_u32(smh + (st * 8 + qt) * 2048);
        uint32_t Kb = smem_u32(smh + (st * 8 + kt) * 2048);
        uint32_t Vb = smem_u32(smh + (st * 8 + vt) * 2048);
        const float* Bp = g_bias + (((a << 3) + h) << 12);

        #pragma unroll 1
        for (int mt = 0; mt < 2; mt++) {
            const int rbase = hf * 32 + mt * 16;
            const int r0 = rbase + gid;

            // ---- S = bias; S += Q K^T ----
            float sacc[8][4];
            #pragma unroll
            for (int nt = 0; nt < 8; nt++) {
                float2 t0 = *(const float2*)(Bp + r0 * 64 + nt * 8 + tig * 2);
                float2 t1 = *(const float2*)(Bp + (r0 + 8) * 64 + nt * 8 + tig * 2);
                sacc[nt][0] = t0.x; sacc[nt][1] = t0.y;
                sacc[nt][2] = t1.x; sacc[nt][3] = t1.y;
            }
            #pragma unroll
            for (int kk = 0; kk < 2; kk++) {
                uint32_t af[4];
                {
                    int row = rbase + (lane & 15);
                    int c4 = kk * 2 + (lane >> 4);
                    LDSM_X4(af, Qb + ((row * 32 + ((c4 ^ ((row >> 1) & 3)) << 3)) << 1));
                }
                #pragma unroll
                for (int ntp = 0; ntp < 4; ntp++) {
                    uint32_t bf[4];
                    int row = ntp * 16 + ((lane >> 4) << 3) + (lane & 7);
                    int c4 = kk * 2 + ((lane >> 3) & 1);
                    LDSM_X4(bf, Kb + ((row * 32 + ((c4 ^ ((row >> 1) & 3)) << 3)) << 1));
                    MMA_16816(sacc[ntp * 2],     af, bf[0], bf[1]);
                    MMA_16816(sacc[ntp * 2 + 1], af, bf[2], bf[3]);
                }
            }

            // ---- softmax (rows r0, r0+8) ----
            float mx0 = -1e30f, mx1 = -1e30f;
            #pragma unroll
            for (int nt = 0; nt < 8; nt++) {
                mx0 = fmaxf(mx0, fmaxf(sacc[nt][0], sacc[nt][1]));
                mx1 = fmaxf(mx1, fmaxf(sacc[nt][2], sacc[nt][3]));
            }
            mx0 = fmaxf(mx0, __shfl_xor_sync(0xffffffffu, mx0, 1));
            mx0 = fmaxf(mx0, __shfl_xor_sync(0xffffffffu, mx0, 2));
            mx1 = fmaxf(mx1, __shfl_xor_sync(0xffffffffu, mx1, 1));
            mx1 = fmaxf(mx1, __shfl_xor_sync(0xffffffffu, mx1, 2));
            const float L2E = 1.4426950408889634f;
            float sum0 = 0.0f, sum1 = 0.0f;
            #pragma unroll
            for (int nt = 0; nt < 8; nt++) {
                sacc[nt][0] = exp2f((sacc[nt][0] - mx0) * L2E);
                sacc[nt][1] = exp2f((sacc[nt][1] - mx0) * L2E);
                sacc[nt][2] = exp2f((sacc[nt][2] - mx1) * L2E);
                sacc[nt][3] = exp2f((sacc[nt][3] - mx1) * L2E);
                sum0 += sacc[nt][0] + sacc[nt][1];
                sum1 += sacc[nt][2] + sacc[nt][3];
            }
            sum0 += __shfl_xor_sync(0xffffffffu, sum0, 1);
            sum0 += __shfl_xor_sync(0xffffffffu, sum0, 2);
            sum1 += __shfl_xor_sync(0xffffffffu, sum1, 1);
            sum1 += __shfl_xor_sync(0xffffffffu, sum1, 2);
            float inv0 = __fdividef(1.0f, sum0);
            float inv1 = __fdividef(1.0f, sum1);

            // ---- P -> fp16 hi/lo packs (A-fragment layout) ----
            uint32_t ph[8][2], pl[8][2];
            #pragma unroll
            for (int nt = 0; nt < 8; nt++) {
                pack_hl(sacc[nt][0], sacc[nt][1], ph[nt][0], pl[nt][0]);
                pack_hl(sacc[nt][2], sacc[nt][3], ph[nt][1], pl[nt][1]);
            }

            // ---- O = P V  (split-precision, V^T tiles) ----
            float oacc[4][4];
            #pragma unroll
            for (int n4 = 0; n4 < 4; n4++)
                #pragma unroll
                for (int r = 0; r < 4; r++) oacc[n4][r] = 0.0f;

            #pragma unroll
            for (int kk = 0; kk < 4; kk++) {
                uint32_t bf[2][4];
                #pragma unroll
                for (int ntp = 0; ntp < 2; ntp++) {
                    int row = ntp * 16 + ((lane >> 4) << 3) + (lane & 7);
                    int c8 = kk * 2 + ((lane >> 3) & 1);
                    LDSM_X4(bf[ntp], Vb + ((row * 64 + ((c8 ^ (row & 7)) << 3)) << 1));
                }
                uint32_t ah[4] = { ph[2 * kk][0], ph[2 * kk][1],
                                   ph[2 * kk + 1][0], ph[2 * kk + 1][1] };
                uint32_t al[4] = { pl[2 * kk][0], pl[2 * kk][1],
                                   pl[2 * kk + 1][0], pl[2 * kk + 1][1] };
                #pragma unroll
                for (int n4 = 0; n4 < 4; n4++) {
                    MMA_16816(oacc[n4], ah, bf[n4 >> 1][(n4 & 1) * 2], bf[n4 >> 1][(n4 & 1) * 2 + 1]);
                    MMA_16816(oacc[n4], al, bf[n4 >> 1][(n4 & 1) * 2], bf[n4 >> 1][(n4 & 1) * 2 + 1]);
                }
            }

            // ---- epilogue: scale by 1/sum, fp16 store ----
            size_t rowg = (size_t)b * 64 + r0;
            #pragma unroll
            for (int n4 = 0; n4 < 4; n4++) {
                int col = cbase + (h << 5) + n4 * 8 + tig * 2;
                __half2 v0 = __floats2half2_rn(oacc[n4][0] * inv0, oacc[n4][1] * inv0);
                __half2 v1 = __floats2half2_rn(oacc[n4][2] * inv1, oacc[n4][3] * inv1);
                *(__half2*)(dst0 + rowg * 512 + col)       = v0;
                *(__half2*)(dst0 + (rowg + 8) * 512 + col) = v1;
            }
        }
        __syncthreads();
    }
}

// ---------------- output projection GEMM ------------------------------------
__global__ __launch_bounds__(256)
void out_gemm(int which, const float* __restrict__ bp, float* __restrict__ out) {
    __shared__ __align__(16) __half SA[2 * 128 * 64];
    __shared__ __align__(16) __half SB[2 * 64 * 64];
    const int mb = blockIdx.x, nb = blockIdx.y;
    const __half* A = which ? g_atth : g_attv;

    float acc[2][4][4];
    hgemm_core<512>(A, g_wpt[which], mb, nb, SA, SB, acc);

    const int tid = threadIdx.x, w = tid >> 5, lane = tid & 31;
    const int wm = (w >> 1) * 32, wn = (w & 1) * 32;
    const int gid = lane >> 2, tig = lane & 3;

    #pragma unroll
    for (int t = 0; t < 2; t++)
        #pragma unroll
        for (int j = 0; j < 4; j++) {
            int n = nb * 64 + wn + j * 8 + tig * 2;       // 0..255
            float b0 = bp[n], b1 = bp[n + 1];
            #pragma unroll
            for (int rr = 0; rr < 2; rr++) {
                int m = mb * 128 + wm + t * 16 + gid + rr * 8;
                float2 v = make_float2(acc[t][j][rr * 2] + b0,
                                       acc[t][j][rr * 2 + 1] + b1);
                *(float2*)(out + (size_t)m * 256 + n) = v;
            }
        }
}

// ---------------- launch -----------------------------------------------------
extern "C" void kernel_launch(void* const* d_in, const int* in_sizes, int n_in,
                              void* d_out, int out_size) {
    const float* input_x = (const float*)d_in[0];
    const float* state_x = (const float*)d_in[1];
    const float* Ws  = (const float*)d_in[2];
    const float* bs  = (const float*)d_in[3];
    const float* We  = (const float*)d_in[4];
    const float* be  = (const float*)d_in[5];
    const float* Wpv = (const float*)d_in[6];
    const float* bpv = (const float*)d_in[7];
    const float* Wph = (const float*)d_in[8];
    const float* bph = (const float*)d_in[9];
    const float* tcv = (const float*)d_in[10];
    const float* tsv = (const float*)d_in[11];
    const float* tch = (const float*)d_in[12];
    const float* tsh = (const float*)d_in[13];
    const int*   rpi = (const int*)d_in[14];
    float* out = (float*)d_out;

    cudaFuncSetAttribute(attn_kernel, cudaFuncAttributeMaxDynamicSharedMemorySize, SM_ATT);

    bias_kernel<<<512, 256>>>(tcv, tsv, tch, tsh, rpi);
    xprep_kernel<<<dim3(16384, 2), 256>>>(input_x, state_x);
    wprep_kernel<<<2048, 256>>>(Ws, We);
    wpprep_kernel<<<1024, 256>>>(Wpv, Wph);

    qkv_gemm<<<dim3(1024, 16, 2), 256>>>(bs, be);
    attn_kernel<<<NWIN, 256, SM_ATT>>>();
    out_gemm<<<dim3(1024, 4), 256>>>(0, bpv, out);
    out_gemm<<<dim3(1024, 4), 256>>>(1, bph, out + BNC);
}

// round 5
// speedup vs baseline: 6.6442x; 1.1167x over previous
#include <cuda_runtime.h>
#include <cuda_fp16.h>
#include <cstdint>
#include <cstddef>

#define HEADS 8
#define NWIN  2048
#define MROWS (NWIN * 64)                   // 131072 token rows
#define BNC   ((size_t)MROWS * 256)         // 33,554,432 output elems per tensor

// ---------------- scratch (device globals; no allocation allowed) ----------
__device__ __half g_wt[2][1024 * 256];              // QKV weights, [src][col][k]
__device__ __half g_wpt[2][256 * 512];              // out-proj weights, [w][n][k]
__device__ __half g_qkv[(size_t)NWIN * 2 * 4 * HEADS * 64 * 32];  // head tiles
__device__ __half g_attv[(size_t)MROWS * 512];      // [cross_v | self_v]
__device__ __half g_atth[(size_t)MROWS * 512];      // [cross_h | self_h]
__device__ float  g_bias[4 * HEADS * 64 * 64];      // 512 KB

// ---------------- helpers ---------------------------------------------------
__device__ __forceinline__ uint32_t smem_u32(const void* p) {
    uint32_t a;
    asm("{ .reg .u64 t; cvta.to.shared.u64 t, %1; cvt.u32.u64 %0, t; }" : "=r"(a) : "l"(p));
    return a;
}
#define CP_ASYNC16(dst, src) \
    asm volatile("cp.async.cg.shared.global [%0], [%1], 16;" :: "r"(dst), "l"(src))
#define CP_COMMIT() asm volatile("cp.async.commit_group;" ::: "memory")

#define LDSM_X4(r, addr) \
    asm volatile("ldmatrix.sync.aligned.m8n8.x4.shared.b16 {%0,%1,%2,%3}, [%4];" \
        : "=r"((r)[0]), "=r"((r)[1]), "=r"((r)[2]), "=r"((r)[3]) : "r"(addr))

#define MMA_16816(c, a, b0, b1) \
    asm volatile("mma.sync.aligned.m16n8k16.row.col.f32.f16.f16.f32 " \
        "{%0,%1,%2,%3}, {%4,%5,%6,%7}, {%8,%9}, {%0,%1,%2,%3};" \
        : "+f"((c)[0]), "+f"((c)[1]), "+f"((c)[2]), "+f"((c)[3]) \
        : "r"((a)[0]), "r"((a)[1]), "r"((a)[2]), "r"((a)[3]), "r"(b0), "r"(b1))

// split a float pair into fp16 high + fp16 low (residual) packs
__device__ __forceinline__ void pack_hl(float x, float y, uint32_t& hi, uint32_t& lo) {
    __half2 h = __floats2half2_rn(x, y);
    float2 r = __half22float2(h);
    __half2 l = __floats2half2_rn(x - r.x, y - r.y);
    hi = *(uint32_t*)&h;
    lo = *(uint32_t*)&l;
}

// ---------------- prep kernels ----------------------------------------------
__global__ void bias_kernel(const float* __restrict__ tcv, const float* __restrict__ tsv,
                            const float* __restrict__ tch, const float* __restrict__ tsh,
                            const int* __restrict__ rpi) {
    int idx = blockIdx.x * blockDim.x + threadIdx.x;   // 131072
    if (idx >= 4 * HEADS * 64 * 64) return;
    int m = idx & 63, n = (idx >> 6) & 63, h = (idx >> 12) & 7, a = idx >> 15;
    const float* tab = (a == 0) ? tcv : (a == 1) ? tsv : (a == 2) ? tch : tsh;
    g_bias[idx] = tab[rpi[n * 64 + m] * HEADS + h];
}

__global__ void wprep_kernel(const float* __restrict__ Ws, const float* __restrict__ We) {
    int idx = blockIdx.x * 256 + threadIdx.x;          // 524288
    int k = idx & 255, c = (idx >> 8) & 1023, src = idx >> 18;
    const float* W = src ? We : Ws;
    g_wt[src][c * 256 + k] = __float2half_rn(W[(size_t)k * 1024 + c]);
}
__global__ void wpprep_kernel(const float* __restrict__ Wpv, const float* __restrict__ Wph) {
    int idx = blockIdx.x * 256 + threadIdx.x;          // 262144
    int k = idx & 511, n = (idx >> 9) & 255, w = idx >> 17;
    const float* W = w ? Wph : Wpv;
    g_wpt[w][n * 512 + k] = __float2half_rn(W[(size_t)k * 256 + n]);
}

// ---------------- QKV projection GEMM (A-resident) ---------------------------
// grid (512 m-blocks, 2 src), 512 threads (16 warps = 8m x 2n of 32x32).
// smem: SA 256x256 fp16 (128 KB, resident) + SB 2 x 64x256 fp16 (64 KB).
#define SM_QKV (196608)

__global__ __launch_bounds__(512)
void qkv_gemm(const float* __restrict__ input_x, const float* __restrict__ state_x,
              const float* __restrict__ bs, const float* __restrict__ be) {
    extern __shared__ __half smh[];
    __half* SA = smh;                       // 65536 halves
    __half* SB = smh + 65536;               // 2 x 16384 halves

    const int tid = threadIdx.x, w = tid >> 5, lane = tid & 31;
    const int mb = blockIdx.x, src = blockIdx.y;
    const int wm = (w >> 1) * 32, wn = (w & 1) * 32;
    const int gid = lane >> 2, tig = lane & 3;

    // ---- A prologue: fp32 global -> fp16 swizzled smem (256 rows x 256 k) ----
    const float4* X4 = (const float4*)(src ? input_x : state_x);
    #pragma unroll
    for (int i = 0; i < 16; i++) {
        int ch = tid + i * 512;             // 8192 chunks of 8 halves
        int r = ch >> 5, c = ch & 31;
        size_t gsrc = ((size_t)(mb * 256 + r) * 256 + c * 8) >> 2;
        float4 v0 = X4[gsrc], v1 = X4[gsrc + 1];
        __half2 h0 = __floats2half2_rn(v0.x, v0.y), h1 = __floats2half2_rn(v0.z, v0.w);
        __half2 h2 = __floats2half2_rn(v1.x, v1.y), h3 = __floats2half2_rn(v1.z, v1.w);
        uint4 u;
        u.x = *(uint32_t*)&h0; u.y = *(uint32_t*)&h1;
        u.z = *(uint32_t*)&h2; u.w = *(uint32_t*)&h3;
        *(uint4*)(SA + r * 256 + ((c ^ (r & 7)) << 3)) = u;
    }

    // ---- B streaming over 16 n-blocks, double-buffered ----
    const __half* Bsrc = g_wt[src];
    auto issueB = [&](int s, int nb) {
        #pragma unroll
        for (int i = 0; i < 4; i++) {
            int ch = tid + i * 512;         // 2048 chunks
            int r = ch >> 5, c = ch & 31;
            uint32_t d = smem_u32(SB + s * 16384 + r * 256 + ((c ^ (r & 7)) << 3));
            CP_ASYNC16(d, Bsrc + (size_t)(nb * 64 + r) * 256 + c * 8);
        }
    };
    issueB(0, 0);
    CP_COMMIT();

    const float* bv = src ? be : bs;
    const float kscale = 0.17677669529663687f;
    const float m2 = src ? 1.0f : kscale;                // qsv / qev
    const float m3 = src ? kscale : kscale * kscale;     // qsh / qeh

    uint32_t baseA = smem_u32(SA);

    #pragma unroll 1
    for (int nb = 0; nb < 16; nb++) {
        int s = nb & 1;
        if (nb + 1 < 16) {
            issueB(s ^ 1, nb + 1);
            CP_COMMIT();
            asm volatile("cp.async.wait_group 1;" ::: "memory");
        } else {
            asm volatile("cp.async.wait_group 0;" ::: "memory");
        }
        __syncthreads();

        float acc[2][4][4];
        #pragma unroll
        for (int t = 0; t < 2; t++)
            #pragma unroll
            for (int j = 0; j < 4; j++)
                #pragma unroll
                for (int r = 0; r < 4; r++) acc[t][j][r] = 0.0f;

        uint32_t baseB = smem_u32(SB + s * 16384);
        #pragma unroll
        for (int ks = 0; ks < 16; ks++) {
            uint32_t af[2][4], bf[2][4];
            #pragma unroll
            for (int t = 0; t < 2; t++) {
                int row = wm + t * 16 + (lane & 15);
                int kc8 = ks * 2 + (lane >> 4);
                LDSM_X4(af[t], baseA + ((row * 256 + ((kc8 ^ (row & 7)) << 3)) << 1));
            }
            #pragma unroll
            for (int p = 0; p < 2; p++) {
                int n   = wn + p * 16 + ((lane >> 4) << 3) + (lane & 7);
                int kc8 = ks * 2 + ((lane >> 3) & 1);
                LDSM_X4(bf[p], baseB + ((n * 256 + ((kc8 ^ (n & 7)) << 3)) << 1));
            }
            #pragma unroll
            for (int t = 0; t < 2; t++)
                #pragma unroll
                for (int j = 0; j < 4; j++)
                    MMA_16816(acc[t][j], af[t],
                              bf[j >> 1][(j & 1) * 2], bf[j >> 1][(j & 1) * 2 + 1]);
        }

        // ---- epilogue: +bias, q-scales, store head tiles (V transposed) ----
        #pragma unroll
        for (int t = 0; t < 2; t++)
            #pragma unroll
            for (int j = 0; j < 4; j++) {
                int nglob = nb * 64 + wn + j * 8 + tig * 2;   // 0..1023
                int f = nglob >> 8, h = (nglob >> 5) & 7, d = nglob & 31;
                float mult = (f == 2) ? m2 : (f == 3) ? m3 : 1.0f;
                float b0 = bv[nglob], b1 = bv[nglob + 1];
                #pragma unroll
                for (int rr = 0; rr < 2; rr++) {
                    int m = mb * 256 + wm + t * 16 + gid + rr * 8;
                    int b = m >> 6, ntok = m & 63;
                    size_t tile = ((((size_t)b * 2 + src) * 4 + f) * 8 + h) * 2048;
                    float v0 = (acc[t][j][rr * 2] + b0) * mult;
                    float v1 = (acc[t][j][rr * 2 + 1] + b1) * mult;
                    if (f == 1) {
                        // V stored transposed: [d][tok] rows of 64 tokens
                        g_qkv[tile + (size_t)d * 64 + ntok]       = __float2half_rn(v0);
                        g_qkv[tile + (size_t)(d + 1) * 64 + ntok] = __float2half_rn(v1);
                    } else {
                        __half2 hv = __floats2half2_rn(v0, v1);
                        *(__half2*)(g_qkv + tile + ntok * 32 + d) = hv;
                    }
                }
            }
        __syncthreads();
    }
}

// ---------------- attention kernel (HMMA flash-style) -----------------------
// CTA = 1 window, 8 warps = 4 attentions x 2 row-halves, loop 8 heads.
#define SM_ATT (2 * 8 * 2048 * 2)

__global__ __launch_bounds__(256, 2)
void attn_kernel() {
    extern __shared__ __half smh[];
    const int b = blockIdx.x, tid = threadIdx.x;
    const int w = tid >> 5, lane = tid & 31;
    const int gid = lane >> 2, tig = lane & 3;
    const int a = w >> 1, hf = w & 1;

    const int qt = (a == 0) ? 2 : (a == 1) ? 6 : (a == 2) ? 7 : 3;
    const int kt = (a == 0 || a == 3) ? 0 : 4;
    const int vt = kt + 1;
    __half* dst0 = (a <= 1) ? g_attv : g_atth;
    const int cbase = (a == 1 || a == 3) ? 256 : 0;

    auto stage = [&](int st, int h) {
        #pragma unroll
        for (int i = 0; i < 8; i++) {
            int ch = tid + i * 256;             // 2048 chunks of 16B
            int t = ch >> 8, c = ch & 255;
            const __half* src = g_qkv +
                ((((size_t)b * 2 + (t >> 2)) * 4 + (t & 3)) * 8 + h) * 2048 + c * 8;
            uint32_t off;
            if ((t & 3) == 1) {                 // V^T tile [32][64]
                int r = c >> 3, c8 = c & 7;
                off = r * 64 + ((c8 ^ (r & 7)) << 3);
            } else {                            // Q/K tile [64][32]
                int r = c >> 2, c4 = c & 3;
                off = r * 32 + ((c4 ^ ((r >> 1) & 3)) << 3);
            }
            CP_ASYNC16(smem_u32(smh + (st * 8 + t) * 2048 + off), src);
        }
    };

    stage(0, 0);
    CP_COMMIT();

    #pragma unroll 1
    for (int h = 0; h < HEADS; h++) {
        int st = h & 1;
        if (h < 7) {
            stage(st ^ 1, h + 1);
            CP_COMMIT();
            asm volatile("cp.async.wait_group 1;" ::: "memory");
        } else {
            asm volatile("cp.async.wait_group 0;" ::: "memory");
        }
        __syncthreads();

        uint32_t Qb = smem_u32(smh + (st * 8 + qt) * 2048);
        uint32_t Kb = smem_u32(smh + (st * 8 + kt) * 2048);
        uint32_t Vb = smem_u32(smh + (st * 8 + vt) * 2048);
        const float* Bp = g_bias + (((a << 3) + h) << 12);

        #pragma unroll 1
        for (int mt = 0; mt < 2; mt++) {
            const int rbase = hf * 32 + mt * 16;
            const int r0 = rbase + gid;

            float sacc[8][4];
            #pragma unroll
            for (int nt = 0; nt < 8; nt++) {
                float2 t0 = *(const float2*)(Bp + r0 * 64 + nt * 8 + tig * 2);
                float2 t1 = *(const float2*)(Bp + (r0 + 8) * 64 + nt * 8 + tig * 2);
                sacc[nt][0] = t0.x; sacc[nt][1] = t0.y;
                sacc[nt][2] = t1.x; sacc[nt][3] = t1.y;
            }
            #pragma unroll
            for (int kk = 0; kk < 2; kk++) {
                uint32_t af[4];
                {
                    int row = rbase + (lane & 15);
                    int c4 = kk * 2 + (lane >> 4);
                    LDSM_X4(af, Qb + ((row * 32 + ((c4 ^ ((row >> 1) & 3)) << 3)) << 1));
                }
                #pragma unroll
                for (int ntp = 0; ntp < 4; ntp++) {
                    uint32_t bf[4];
                    int row = ntp * 16 + ((lane >> 4) << 3) + (lane & 7);
                    int c4 = kk * 2 + ((lane >> 3) & 1);
                    LDSM_X4(bf, Kb + ((row * 32 + ((c4 ^ ((row >> 1) & 3)) << 3)) << 1));
                    MMA_16816(sacc[ntp * 2],     af, bf[0], bf[1]);
                    MMA_16816(sacc[ntp * 2 + 1], af, bf[2], bf[3]);
                }
            }

            float mx0 = -1e30f, mx1 = -1e30f;
            #pragma unroll
            for (int nt = 0; nt < 8; nt++) {
                mx0 = fmaxf(mx0, fmaxf(sacc[nt][0], sacc[nt][1]));
                mx1 = fmaxf(mx1, fmaxf(sacc[nt][2], sacc[nt][3]));
            }
            mx0 = fmaxf(mx0, __shfl_xor_sync(0xffffffffu, mx0, 1));
            mx0 = fmaxf(mx0, __shfl_xor_sync(0xffffffffu, mx0, 2));
            mx1 = fmaxf(mx1, __shfl_xor_sync(0xffffffffu, mx1, 1));
            mx1 = fmaxf(mx1, __shfl_xor_sync(0xffffffffu, mx1, 2));
            const float L2E = 1.4426950408889634f;
            float sum0 = 0.0f, sum1 = 0.0f;
            #pragma unroll
            for (int nt = 0; nt < 8; nt++) {
                sacc[nt][0] = exp2f((sacc[nt][0] - mx0) * L2E);
                sacc[nt][1] = exp2f((sacc[nt][1] - mx0) * L2E);
                sacc[nt][2] = exp2f((sacc[nt][2] - mx1) * L2E);
                sacc[nt][3] = exp2f((sacc[nt][3] - mx1) * L2E);
                sum0 += sacc[nt][0] + sacc[nt][1];
                sum1 += sacc[nt][2] + sacc[nt][3];
            }
            sum0 += __shfl_xor_sync(0xffffffffu, sum0, 1);
            sum0 += __shfl_xor_sync(0xffffffffu, sum0, 2);
            sum1 += __shfl_xor_sync(0xffffffffu, sum1, 1);
            sum1 += __shfl_xor_sync(0xffffffffu, sum1, 2);
            float inv0 = __fdividef(1.0f, sum0);
            float inv1 = __fdividef(1.0f, sum1);

            uint32_t ph[8][2], pl[8][2];
            #pragma unroll
            for (int nt = 0; nt < 8; nt++) {
                pack_hl(sacc[nt][0], sacc[nt][1], ph[nt][0], pl[nt][0]);
                pack_hl(sacc[nt][2], sacc[nt][3], ph[nt][1], pl[nt][1]);
            }

            float oacc[4][4];
            #pragma unroll
            for (int n4 = 0; n4 < 4; n4++)
                #pragma unroll
                for (int r = 0; r < 4; r++) oacc[n4][r] = 0.0f;

            #pragma unroll
            for (int kk = 0; kk < 4; kk++) {
                uint32_t bf[2][4];
                #pragma unroll
                for (int ntp = 0; ntp < 2; ntp++) {
                    int row = ntp * 16 + ((lane >> 4) << 3) + (lane & 7);
                    int c8 = kk * 2 + ((lane >> 3) & 1);
                    LDSM_X4(bf[ntp], Vb + ((row * 64 + ((c8 ^ (row & 7)) << 3)) << 1));
                }
                uint32_t ah[4] = { ph[2 * kk][0], ph[2 * kk][1],
                                   ph[2 * kk + 1][0], ph[2 * kk + 1][1] };
                uint32_t al[4] = { pl[2 * kk][0], pl[2 * kk][1],
                                   pl[2 * kk + 1][0], pl[2 * kk + 1][1] };
                #pragma unroll
                for (int n4 = 0; n4 < 4; n4++) {
                    MMA_16816(oacc[n4], ah, bf[n4 >> 1][(n4 & 1) * 2], bf[n4 >> 1][(n4 & 1) * 2 + 1]);
                    MMA_16816(oacc[n4], al, bf[n4 >> 1][(n4 & 1) * 2], bf[n4 >> 1][(n4 & 1) * 2 + 1]);
                }
            }

            size_t rowg = (size_t)b * 64 + r0;
            #pragma unroll
            for (int n4 = 0; n4 < 4; n4++) {
                int col = cbase + (h << 5) + n4 * 8 + tig * 2;
                __half2 v0 = __floats2half2_rn(oacc[n4][0] * inv0, oacc[n4][1] * inv0);
                __half2 v1 = __floats2half2_rn(oacc[n4][2] * inv1, oacc[n4][3] * inv1);
                *(__half2*)(dst0 + rowg * 512 + col)       = v0;
                *(__half2*)(dst0 + (rowg + 8) * 512 + col) = v1;
            }
        }
        __syncthreads();
    }
}

// ---------------- output projection GEMM ------------------------------------
__global__ __launch_bounds__(256)
void out_gemm(int which, const float* __restrict__ bp, float* __restrict__ out) {
    __shared__ __align__(16) __half SA[2 * 128 * 64];
    __shared__ __align__(16) __half SB[2 * 64 * 64];
    const int mb = blockIdx.x, nb = blockIdx.y;
    const __half* A = which ? g_atth : g_attv;
    const __half* B = g_wpt[which];

    const int tid = threadIdx.x, w = tid >> 5, lane = tid & 31;
    const int wm = (w >> 1) * 32, wn = (w & 1) * 32;

    float acc[2][4][4];
    #pragma unroll
    for (int t = 0; t < 2; t++)
        #pragma unroll
        for (int j = 0; j < 4; j++)
            #pragma unroll
            for (int r = 0; r < 4; r++) acc[t][j][r] = 0.0f;

    auto issue = [&](int s, int kc) {
        __half* sa = SA + s * (128 * 64);
        __half* sb = SB + s * (64 * 64);
        #pragma unroll
        for (int i = 0; i < 4; i++) {
            int ch = tid + i * 256, r = ch >> 3, k8 = ch & 7;
            uint32_t d = smem_u32(sa + r * 64 + ((k8 ^ (r & 7)) << 3));
            CP_ASYNC16(d, A + (size_t)(mb * 128 + r) * 512 + kc * 64 + k8 * 8);
        }
        #pragma unroll
        for (int i = 0; i < 2; i++) {
            int ch = tid + i * 256, r = ch >> 3, k8 = ch & 7;
            uint32_t d = smem_u32(sb + r * 64 + ((k8 ^ (r & 7)) << 3));
            CP_ASYNC16(d, B + (size_t)(nb * 64 + r) * 512 + kc * 64 + k8 * 8);
        }
    };
    issue(0, 0);
    CP_COMMIT();

    #pragma unroll 1
    for (int kc = 0; kc < 8; kc++) {
        int s = kc & 1;
        if (kc + 1 < 8) {
            issue(s ^ 1, kc + 1);
            CP_COMMIT();
            asm volatile("cp.async.wait_group 1;" ::: "memory");
        } else {
            asm volatile("cp.async.wait_group 0;" ::: "memory");
        }
        __syncthreads();

        uint32_t baseA = smem_u32(SA + s * (128 * 64));
        uint32_t baseB = smem_u32(SB + s * (64 * 64));
        #pragma unroll
        for (int ks = 0; ks < 4; ks++) {
            uint32_t af[2][4], bf[2][4];
            #pragma unroll
            for (int t = 0; t < 2; t++) {
                int row = wm + t * 16 + (lane & 15);
                int kc8 = ks * 2 + (lane >> 4);
                LDSM_X4(af[t], baseA + ((row * 64 + ((kc8 ^ (row & 7)) << 3)) << 1));
            }
            #pragma unroll
            for (int p = 0; p < 2; p++) {
                int n   = wn + p * 16 + ((lane >> 4) << 3) + (lane & 7);
                int kc8 = ks * 2 + ((lane >> 3) & 1);
                LDSM_X4(bf[p], baseB + ((n * 64 + ((kc8 ^ (n & 7)) << 3)) << 1));
            }
            #pragma unroll
            for (int t = 0; t < 2; t++)
                #pragma unroll
                for (int j = 0; j < 4; j++)
                    MMA_16816(acc[t][j], af[t],
                              bf[j >> 1][(j & 1) * 2], bf[j >> 1][(j & 1) * 2 + 1]);
        }
        __syncthreads();
    }

    const int gid = lane >> 2, tig = lane & 3;
    #pragma unroll
    for (int t = 0; t < 2; t++)
        #pragma unroll
        for (int j = 0; j < 4; j++) {
            int n = nb * 64 + wn + j * 8 + tig * 2;       // 0..255
            float b0 = bp[n], b1 = bp[n + 1];
            #pragma unroll
            for (int rr = 0; rr < 2; rr++) {
                int m = mb * 128 + wm + t * 16 + gid + rr * 8;
                float2 v = make_float2(acc[t][j][rr * 2] + b0,
                                       acc[t][j][rr * 2 + 1] + b1);
                *(float2*)(out + (size_t)m * 256 + n) = v;
            }
        }
}

// ---------------- launch -----------------------------------------------------
extern "C" void kernel_launch(void* const* d_in, const int* in_sizes, int n_in,
                              void* d_out, int out_size) {
    const float* input_x = (const float*)d_in[0];
    const float* state_x = (const float*)d_in[1];
    const float* Ws  = (const float*)d_in[2];
    const float* bs  = (const float*)d_in[3];
    const float* We  = (const float*)d_in[4];
    const float* be  = (const float*)d_in[5];
    const float* Wpv = (const float*)d_in[6];
    const float* bpv = (const float*)d_in[7];
    const float* Wph = (const float*)d_in[8];
    const float* bph = (const float*)d_in[9];
    const float* tcv = (const float*)d_in[10];
    const float* tsv = (const float*)d_in[11];
    const float* tch = (const float*)d_in[12];
    const float* tsh = (const float*)d_in[13];
    const int*   rpi = (const int*)d_in[14];
    float* out = (float*)d_out;

    cudaFuncSetAttribute(qkv_gemm, cudaFuncAttributeMaxDynamicSharedMemorySize, SM_QKV);
    cudaFuncSetAttribute(attn_kernel, cudaFuncAttributeMaxDynamicSharedMemorySize, SM_ATT);

    bias_kernel<<<512, 256>>>(tcv, tsv, tch, tsh, rpi);
    wprep_kernel<<<2048, 256>>>(Ws, We);
    wpprep_kernel<<<1024, 256>>>(Wpv, Wph);

    qkv_gemm<<<dim3(512, 2), 512, SM_QKV>>>(input_x, state_x, bs, be);
    attn_kernel<<<NWIN, 256, SM_ATT>>>();
    out_gemm<<<dim3(1024, 4), 256>>>(0, bpv, out);
    out_gemm<<<dim3(1024, 4), 256>>>(1, bph, out + BNC);
}

// round 6
// speedup vs baseline: 6.8220x; 1.0268x over previous
#include <cuda_runtime.h>
#include <cuda_fp16.h>
#include <cstdint>
#include <cstddef>

#define HEADS 8
#define NWIN  2048
#define MROWS (NWIN * 64)                   // 131072 token rows
#define BNC   ((size_t)MROWS * 256)         // 33,554,432 output elems per tensor

// ---------------- scratch (device globals; no allocation allowed) ----------
__device__ __half g_wt[2][1024 * 256];              // QKV weights, [src][col][k]
__device__ __half g_wpt[2][256 * 512];              // out-proj weights, [w][n][k]
__device__ __half g_qkv[(size_t)NWIN * 2 * 4 * HEADS * 64 * 32];  // head tiles
__device__ __half g_attv[(size_t)MROWS * 512];      // [cross_v | self_v]
__device__ __half g_atth[(size_t)MROWS * 512];      // [cross_h | self_h]
__device__ float  g_bias[4 * HEADS * 64 * 64];      // 512 KB

// ---------------- helpers ---------------------------------------------------
__device__ __forceinline__ uint32_t smem_u32(const void* p) {
    uint32_t a;
    asm("{ .reg .u64 t; cvta.to.shared.u64 t, %1; cvt.u32.u64 %0, t; }" : "=r"(a) : "l"(p));
    return a;
}
#define CP_ASYNC16(dst, src) \
    asm volatile("cp.async.cg.shared.global [%0], [%1], 16;" :: "r"(dst), "l"(src))
#define CP_COMMIT() asm volatile("cp.async.commit_group;" ::: "memory")

#define LDSM_X4(r, addr) \
    asm volatile("ldmatrix.sync.aligned.m8n8.x4.shared.b16 {%0,%1,%2,%3}, [%4];" \
        : "=r"((r)[0]), "=r"((r)[1]), "=r"((r)[2]), "=r"((r)[3]) : "r"(addr))

#define LDSM_X4_T(r, addr) \
    asm volatile("ldmatrix.sync.aligned.m8n8.x4.trans.shared.b16 {%0,%1,%2,%3}, [%4];" \
        : "=r"((r)[0]), "=r"((r)[1]), "=r"((r)[2]), "=r"((r)[3]) : "r"(addr))

#define MMA_16816(c, a, b0, b1) \
    asm volatile("mma.sync.aligned.m16n8k16.row.col.f32.f16.f16.f32 " \
        "{%0,%1,%2,%3}, {%4,%5,%6,%7}, {%8,%9}, {%0,%1,%2,%3};" \
        : "+f"((c)[0]), "+f"((c)[1]), "+f"((c)[2]), "+f"((c)[3]) \
        : "r"((a)[0]), "r"((a)[1]), "r"((a)[2]), "r"((a)[3]), "r"(b0), "r"(b1))

// split a float pair into fp16 high + fp16 low (residual) packs
__device__ __forceinline__ void pack_hl(float x, float y, uint32_t& hi, uint32_t& lo) {
    __half2 h = __floats2half2_rn(x, y);
    float2 r = __half22float2(h);
    __half2 l = __floats2half2_rn(x - r.x, y - r.y);
    hi = *(uint32_t*)&h;
    lo = *(uint32_t*)&l;
}

// ---------------- prep kernels ----------------------------------------------
__global__ void bias_kernel(const float* __restrict__ tcv, const float* __restrict__ tsv,
                            const float* __restrict__ tch, const float* __restrict__ tsh,
                            const int* __restrict__ rpi) {
    int idx = blockIdx.x * blockDim.x + threadIdx.x;   // 131072
    if (idx >= 4 * HEADS * 64 * 64) return;
    int m = idx & 63, n = (idx >> 6) & 63, h = (idx >> 12) & 7, a = idx >> 15;
    const float* tab = (a == 0) ? tcv : (a == 1) ? tsv : (a == 2) ? tch : tsh;
    g_bias[idx] = tab[rpi[n * 64 + m] * HEADS + h];
}

__global__ void wprep_kernel(const float* __restrict__ Ws, const float* __restrict__ We) {
    int idx = blockIdx.x * 256 + threadIdx.x;          // 524288
    int k = idx & 255, c = (idx >> 8) & 1023, src = idx >> 18;
    const float* W = src ? We : Ws;
    g_wt[src][c * 256 + k] = __float2half_rn(W[(size_t)k * 1024 + c]);
}
__global__ void wpprep_kernel(const float* __restrict__ Wpv, const float* __restrict__ Wph) {
    int idx = blockIdx.x * 256 + threadIdx.x;          // 262144
    int k = idx & 511, n = (idx >> 9) & 255, w = idx >> 17;
    const float* W = w ? Wph : Wpv;
    g_wpt[w][n * 512 + k] = __float2half_rn(W[(size_t)k * 256 + n]);
}

// ---------------- QKV projection GEMM (A-resident) ---------------------------
// grid (512 m-blocks, 2 src), 512 threads (16 warps = 8m x 2n of 32x32).
// smem: SA 256x256 fp16 (128 KB, resident) + SB 2 x 64x256 fp16 (64 KB).
#define SM_QKV (196608)

__global__ __launch_bounds__(512)
void qkv_gemm(const float* __restrict__ input_x, const float* __restrict__ state_x,
              const float* __restrict__ bs, const float* __restrict__ be) {
    extern __shared__ __half smh[];
    __half* SA = smh;                       // 65536 halves
    __half* SB = smh + 65536;               // 2 x 16384 halves

    const int tid = threadIdx.x, w = tid >> 5, lane = tid & 31;
    const int mb = blockIdx.x, src = blockIdx.y;
    const int wm = (w >> 1) * 32, wn = (w & 1) * 32;
    const int gid = lane >> 2, tig = lane & 3;

    // ---- A prologue: fp32 global -> fp16 swizzled smem (256 rows x 256 k) ----
    const float4* X4 = (const float4*)(src ? input_x : state_x);
    #pragma unroll
    for (int i = 0; i < 16; i++) {
        int ch = tid + i * 512;             // 8192 chunks of 8 halves
        int r = ch >> 5, c = ch & 31;
        size_t gsrc = ((size_t)(mb * 256 + r) * 256 + c * 8) >> 2;
        float4 v0 = X4[gsrc], v1 = X4[gsrc + 1];
        __half2 h0 = __floats2half2_rn(v0.x, v0.y), h1 = __floats2half2_rn(v0.z, v0.w);
        __half2 h2 = __floats2half2_rn(v1.x, v1.y), h3 = __floats2half2_rn(v1.z, v1.w);
        uint4 u;
        u.x = *(uint32_t*)&h0; u.y = *(uint32_t*)&h1;
        u.z = *(uint32_t*)&h2; u.w = *(uint32_t*)&h3;
        *(uint4*)(SA + r * 256 + ((c ^ (r & 7)) << 3)) = u;
    }

    // ---- B streaming over 16 n-blocks, double-buffered ----
    const __half* Bsrc = g_wt[src];
    auto issueB = [&](int s, int nb) {
        #pragma unroll
        for (int i = 0; i < 4; i++) {
            int ch = tid + i * 512;         // 2048 chunks
            int r = ch >> 5, c = ch & 31;
            uint32_t d = smem_u32(SB + s * 16384 + r * 256 + ((c ^ (r & 7)) << 3));
            CP_ASYNC16(d, Bsrc + (size_t)(nb * 64 + r) * 256 + c * 8);
        }
    };
    issueB(0, 0);
    CP_COMMIT();

    const float* bv = src ? be : bs;
    const float kscale = 0.17677669529663687f;
    const float m2 = src ? 1.0f : kscale;                // qsv / qev
    const float m3 = src ? kscale : kscale * kscale;     // qsh / qeh

    uint32_t baseA = smem_u32(SA);

    #pragma unroll 1
    for (int nb = 0; nb < 16; nb++) {
        int s = nb & 1;
        if (nb + 1 < 16) {
            issueB(s ^ 1, nb + 1);
            CP_COMMIT();
            asm volatile("cp.async.wait_group 1;" ::: "memory");
        } else {
            asm volatile("cp.async.wait_group 0;" ::: "memory");
        }
        __syncthreads();

        float acc[2][4][4];
        #pragma unroll
        for (int t = 0; t < 2; t++)
            #pragma unroll
            for (int j = 0; j < 4; j++)
                #pragma unroll
                for (int r = 0; r < 4; r++) acc[t][j][r] = 0.0f;

        uint32_t baseB = smem_u32(SB + s * 16384);
        #pragma unroll
        for (int ks = 0; ks < 16; ks++) {
            uint32_t af[2][4], bf[2][4];
            #pragma unroll
            for (int t = 0; t < 2; t++) {
                int row = wm + t * 16 + (lane & 15);
                int kc8 = ks * 2 + (lane >> 4);
                LDSM_X4(af[t], baseA + ((row * 256 + ((kc8 ^ (row & 7)) << 3)) << 1));
            }
            #pragma unroll
            for (int p = 0; p < 2; p++) {
                int n   = wn + p * 16 + ((lane >> 4) << 3) + (lane & 7);
                int kc8 = ks * 2 + ((lane >> 3) & 1);
                LDSM_X4(bf[p], baseB + ((n * 256 + ((kc8 ^ (n & 7)) << 3)) << 1));
            }
            #pragma unroll
            for (int t = 0; t < 2; t++)
                #pragma unroll
                for (int j = 0; j < 4; j++)
                    MMA_16816(acc[t][j], af[t],
                              bf[j >> 1][(j & 1) * 2], bf[j >> 1][(j & 1) * 2 + 1]);
        }

        // ---- epilogue: +bias, q-scales, uniform coalesced half2 stores ----
        #pragma unroll
        for (int t = 0; t < 2; t++)
            #pragma unroll
            for (int j = 0; j < 4; j++) {
                int nglob = nb * 64 + wn + j * 8 + tig * 2;   // 0..1023
                int f = nglob >> 8, h = (nglob >> 5) & 7, d = nglob & 31;
                float mult = (f == 2) ? m2 : (f == 3) ? m3 : 1.0f;
                float b0 = bv[nglob], b1 = bv[nglob + 1];
                #pragma unroll
                for (int rr = 0; rr < 2; rr++) {
                    int m = mb * 256 + wm + t * 16 + gid + rr * 8;
                    int b = m >> 6, ntok = m & 63;
                    size_t tile = ((((size_t)b * 2 + src) * 4 + f) * 8 + h) * 2048;
                    __half2 hv = __floats2half2_rn((acc[t][j][rr * 2] + b0) * mult,
                                                   (acc[t][j][rr * 2 + 1] + b1) * mult);
                    *(__half2*)(g_qkv + tile + ntok * 32 + d) = hv;
                }
            }
        __syncthreads();
    }
}

// ---------------- attention kernel (HMMA flash-style) -----------------------
// CTA = 1 window, 8 warps = 4 attentions x 2 row-halves, loop 8 heads.
// All 8 tiles uniform [64 tok][32 d] layout; V loaded via ldmatrix.trans.
#define SM_ATT (2 * 8 * 2048 * 2)

__global__ __launch_bounds__(256, 2)
void attn_kernel() {
    extern __shared__ __half smh[];
    const int b = blockIdx.x, tid = threadIdx.x;
    const int w = tid >> 5, lane = tid & 31;
    const int gid = lane >> 2, tig = lane & 3;
    const int a = w >> 1, hf = w & 1;

    const int qt = (a == 0) ? 2 : (a == 1) ? 6 : (a == 2) ? 7 : 3;
    const int kt = (a == 0 || a == 3) ? 0 : 4;
    const int vt = kt + 1;
    __half* dst0 = (a <= 1) ? g_attv : g_atth;
    const int cbase = (a == 1 || a == 3) ? 256 : 0;

    auto stage = [&](int st, int h) {
        #pragma unroll
        for (int i = 0; i < 8; i++) {
            int ch = tid + i * 256;             // 2048 chunks of 16B
            int t = ch >> 8, c = ch & 255;
            const __half* src = g_qkv +
                ((((size_t)b * 2 + (t >> 2)) * 4 + (t & 3)) * 8 + h) * 2048 + c * 8;
            int r = c >> 2, c4 = c & 3;
            uint32_t off = r * 32 + ((c4 ^ ((r >> 1) & 3)) << 3);
            CP_ASYNC16(smem_u32(smh + (st * 8 + t) * 2048 + off), src);
        }
    };

    stage(0, 0);
    CP_COMMIT();

    #pragma unroll 1
    for (int h = 0; h < HEADS; h++) {
        int st = h & 1;
        if (h < 7) {
            stage(st ^ 1, h + 1);
            CP_COMMIT();
            asm volatile("cp.async.wait_group 1;" ::: "memory");
        } else {
            asm volatile("cp.async.wait_group 0;" ::: "memory");
        }
        __syncthreads();

        uint32_t Qb = smem_u32(smh + (st * 8 + qt) * 2048);
        uint32_t Kb = smem_u32(smh + (st * 8 + kt) * 2048);
        uint32_t Vb = smem_u32(smh + (st * 8 + vt) * 2048);
        const float* Bp = g_bias + (((a << 3) + h) << 12);

        #pragma unroll 1
        for (int mt = 0; mt < 2; mt++) {
            const int rbase = hf * 32 + mt * 16;
            const int r0 = rbase + gid;

            float sacc[8][4];
            #pragma unroll
            for (int nt = 0; nt < 8; nt++) {
                float2 t0 = *(const float2*)(Bp + r0 * 64 + nt * 8 + tig * 2);
                float2 t1 = *(const float2*)(Bp + (r0 + 8) * 64 + nt * 8 + tig * 2);
                sacc[nt][0] = t0.x; sacc[nt][1] = t0.y;
                sacc[nt][2] = t1.x; sacc[nt][3] = t1.y;
            }
            #pragma unroll
            for (int kk = 0; kk < 2; kk++) {
                uint32_t af[4];
                {
                    int row = rbase + (lane & 15);
                    int c4 = kk * 2 + (lane >> 4);
                    LDSM_X4(af, Qb + ((row * 32 + ((c4 ^ ((row >> 1) & 3)) << 3)) << 1));
                }
                #pragma unroll
                for (int ntp = 0; ntp < 4; ntp++) {
                    uint32_t bf[4];
                    int row = ntp * 16 + ((lane >> 4) << 3) + (lane & 7);
                    int c4 = kk * 2 + ((lane >> 3) & 1);
                    LDSM_X4(bf, Kb + ((row * 32 + ((c4 ^ ((row >> 1) & 3)) << 3)) << 1));
                    MMA_16816(sacc[ntp * 2],     af, bf[0], bf[1]);
                    MMA_16816(sacc[ntp * 2 + 1], af, bf[2], bf[3]);
                }
            }

            float mx0 = -1e30f, mx1 = -1e30f;
            #pragma unroll
            for (int nt = 0; nt < 8; nt++) {
                mx0 = fmaxf(mx0, fmaxf(sacc[nt][0], sacc[nt][1]));
                mx1 = fmaxf(mx1, fmaxf(sacc[nt][2], sacc[nt][3]));
            }
            mx0 = fmaxf(mx0, __shfl_xor_sync(0xffffffffu, mx0, 1));
            mx0 = fmaxf(mx0, __shfl_xor_sync(0xffffffffu, mx0, 2));
            mx1 = fmaxf(mx1, __shfl_xor_sync(0xffffffffu, mx1, 1));
            mx1 = fmaxf(mx1, __shfl_xor_sync(0xffffffffu, mx1, 2));
            const float L2E = 1.4426950408889634f;
            float sum0 = 0.0f, sum1 = 0.0f;
            #pragma unroll
            for (int nt = 0; nt < 8; nt++) {
                sacc[nt][0] = exp2f((sacc[nt][0] - mx0) * L2E);
                sacc[nt][1] = exp2f((sacc[nt][1] - mx0) * L2E);
                sacc[nt][2] = exp2f((sacc[nt][2] - mx1) * L2E);
                sacc[nt][3] = exp2f((sacc[nt][3] - mx1) * L2E);
                sum0 += sacc[nt][0] + sacc[nt][1];
                sum1 += sacc[nt][2] + sacc[nt][3];
            }
            sum0 += __shfl_xor_sync(0xffffffffu, sum0, 1);
            sum0 += __shfl_xor_sync(0xffffffffu, sum0, 2);
            sum1 += __shfl_xor_sync(0xffffffffu, sum1, 1);
            sum1 += __shfl_xor_sync(0xffffffffu, sum1, 2);
            float inv0 = __fdividef(1.0f, sum0);
            float inv1 = __fdividef(1.0f, sum1);

            uint32_t ph[8][2], pl[8][2];
            #pragma unroll
            for (int nt = 0; nt < 8; nt++) {
                pack_hl(sacc[nt][0], sacc[nt][1], ph[nt][0], pl[nt][0]);
                pack_hl(sacc[nt][2], sacc[nt][3], ph[nt][1], pl[nt][1]);
            }

            float oacc[4][4];
            #pragma unroll
            for (int n4 = 0; n4 < 4; n4++)
                #pragma unroll
                for (int r = 0; r < 4; r++) oacc[n4][r] = 0.0f;

            #pragma unroll
            for (int kk = 0; kk < 4; kk++) {
                uint32_t bf[2][4];
                #pragma unroll
                for (int ntp = 0; ntp < 2; ntp++) {
                    // trans-load of V[tok][d]: B-fragments for k=tok, n=d
                    int row = kk * 16 + ((lane >> 3) & 1) * 8 + (lane & 7);
                    int c4 = ntp * 2 + ((lane >> 4) & 1);
                    LDSM_X4_T(bf[ntp], Vb + ((row * 32 + ((c4 ^ ((row >> 1) & 3)) << 3)) << 1));
                }
                uint32_t ah[4] = { ph[2 * kk][0], ph[2 * kk][1],
                                   ph[2 * kk + 1][0], ph[2 * kk + 1][1] };
                uint32_t al[4] = { pl[2 * kk][0], pl[2 * kk][1],
                                   pl[2 * kk + 1][0], pl[2 * kk + 1][1] };
                #pragma unroll
                for (int n4 = 0; n4 < 4; n4++) {
                    MMA_16816(oacc[n4], ah, bf[n4 >> 1][(n4 & 1) * 2], bf[n4 >> 1][(n4 & 1) * 2 + 1]);
                    MMA_16816(oacc[n4], al, bf[n4 >> 1][(n4 & 1) * 2], bf[n4 >> 1][(n4 & 1) * 2 + 1]);
                }
            }

            size_t rowg = (size_t)b * 64 + r0;
            #pragma unroll
            for (int n4 = 0; n4 < 4; n4++) {
                int col = cbase + (h << 5) + n4 * 8 + tig * 2;
                __half2 v0 = __floats2half2_rn(oacc[n4][0] * inv0, oacc[n4][1] * inv0);
                __half2 v1 = __floats2half2_rn(oacc[n4][2] * inv1, oacc[n4][3] * inv1);
                *(__half2*)(dst0 + rowg * 512 + col)       = v0;
                *(__half2*)(dst0 + (rowg + 8) * 512 + col) = v1;
            }
        }
        __syncthreads();
    }
}

// ---------------- output projection GEMM (both tensors, grid.z) --------------
__global__ __launch_bounds__(256)
void out_gemm(const float* __restrict__ bpv, const float* __restrict__ bph,
              float* __restrict__ out) {
    __shared__ __align__(16) __half SA[2 * 128 * 64];
    __shared__ __align__(16) __half SB[2 * 64 * 64];
    const int mb = blockIdx.x, nb = blockIdx.y, which = blockIdx.z;
    const __half* A = which ? g_atth : g_attv;
    const __half* B = g_wpt[which];
    const float* bp = which ? bph : bpv;
    float* dst = out + (size_t)which * BNC;

    const int tid = threadIdx.x, w = tid >> 5, lane = tid & 31;
    const int wm = (w >> 1) * 32, wn = (w & 1) * 32;

    float acc[2][4][4];
    #pragma unroll
    for (int t = 0; t < 2; t++)
        #pragma unroll
        for (int j = 0; j < 4; j++)
            #pragma unroll
            for (int r = 0; r < 4; r++) acc[t][j][r] = 0.0f;

    auto issue = [&](int s, int kc) {
        __half* sa = SA + s * (128 * 64);
        __half* sb = SB + s * (64 * 64);
        #pragma unroll
        for (int i = 0; i < 4; i++) {
            int ch = tid + i * 256, r = ch >> 3, k8 = ch & 7;
            uint32_t d = smem_u32(sa + r * 64 + ((k8 ^ (r & 7)) << 3));
            CP_ASYNC16(d, A + (size_t)(mb * 128 + r) * 512 + kc * 64 + k8 * 8);
        }
        #pragma unroll
        for (int i = 0; i < 2; i++) {
            int ch = tid + i * 256, r = ch >> 3, k8 = ch & 7;
            uint32_t d = smem_u32(sb + r * 64 + ((k8 ^ (r & 7)) << 3));
            CP_ASYNC16(d, B + (size_t)(nb * 64 + r) * 512 + kc * 64 + k8 * 8);
        }
    };
    issue(0, 0);
    CP_COMMIT();

    #pragma unroll 1
    for (int kc = 0; kc < 8; kc++) {
        int s = kc & 1;
        if (kc + 1 < 8) {
            issue(s ^ 1, kc + 1);
            CP_COMMIT();
            asm volatile("cp.async.wait_group 1;" ::: "memory");
        } else {
            asm volatile("cp.async.wait_group 0;" ::: "memory");
        }
        __syncthreads();

        uint32_t baseA = smem_u32(SA + s * (128 * 64));
        uint32_t baseB = smem_u32(SB + s * (64 * 64));
        #pragma unroll
        for (int ks = 0; ks < 4; ks++) {
            uint32_t af[2][4], bf[2][4];
            #pragma unroll
            for (int t = 0; t < 2; t++) {
                int row = wm + t * 16 + (lane & 15);
                int kc8 = ks * 2 + (lane >> 4);
                LDSM_X4(af[t], baseA + ((row * 64 + ((kc8 ^ (row & 7)) << 3)) << 1));
            }
            #pragma unroll
            for (int p = 0; p < 2; p++) {
                int n   = wn + p * 16 + ((lane >> 4) << 3) + (lane & 7);
                int kc8 = ks * 2 + ((lane >> 3) & 1);
                LDSM_X4(bf[p], baseB + ((n * 64 + ((kc8 ^ (n & 7)) << 3)) << 1));
            }
            #pragma unroll
            for (int t = 0; t < 2; t++)
                #pragma unroll
                for (int j = 0; j < 4; j++)
                    MMA_16816(acc[t][j], af[t],
                              bf[j >> 1][(j & 1) * 2], bf[j >> 1][(j & 1) * 2 + 1]);
        }
        __syncthreads();
    }

    const int gid = lane >> 2, tig = lane & 3;
    #pragma unroll
    for (int t = 0; t < 2; t++)
        #pragma unroll
        for (int j = 0; j < 4; j++) {
            int n = nb * 64 + wn + j * 8 + tig * 2;       // 0..255
            float b0 = bp[n], b1 = bp[n + 1];
            #pragma unroll
            for (int rr = 0; rr < 2; rr++) {
                int m = mb * 128 + wm + t * 16 + gid + rr * 8;
                float2 v = make_float2(acc[t][j][rr * 2] + b0,
                                       acc[t][j][rr * 2 + 1] + b1);
                *(float2*)(dst + (size_t)m * 256 + n) = v;
            }
        }
}

// ---------------- launch -----------------------------------------------------
extern "C" void kernel_launch(void* const* d_in, const int* in_sizes, int n_in,
                              void* d_out, int out_size) {
    const float* input_x = (const float*)d_in[0];
    const float* state_x = (const float*)d_in[1];
    const float* Ws  = (const float*)d_in[2];
    const float* bs  = (const float*)d_in[3];
    const float* We  = (const float*)d_in[4];
    const float* be  = (const float*)d_in[5];
    const float* Wpv = (const float*)d_in[6];
    const float* bpv = (const float*)d_in[7];
    const float* Wph = (const float*)d_in[8];
    const float* bph = (const float*)d_in[9];
    const float* tcv = (const float*)d_in[10];
    const float* tsv = (const float*)d_in[11];
    const float* tch = (const float*)d_in[12];
    const float* tsh = (const float*)d_in[13];
    const int*   rpi = (const int*)d_in[14];
    float* out = (float*)d_out;

    cudaFuncSetAttribute(qkv_gemm, cudaFuncAttributeMaxDynamicSharedMemorySize, SM_QKV);
    cudaFuncSetAttribute(attn_kernel, cudaFuncAttributeMaxDynamicSharedMemorySize, SM_ATT);

    bias_kernel<<<512, 256>>>(tcv, tsv, tch, tsh, rpi);
    wprep_kernel<<<2048, 256>>>(Ws, We);
    wpprep_kernel<<<1024, 256>>>(Wpv, Wph);

    qkv_gemm<<<dim3(512, 2), 512, SM_QKV>>>(input_x, state_x, bs, be);
    attn_kernel<<<NWIN, 256, SM_ATT>>>();
    out_gemm<<<dim3(1024, 4, 2), 256>>>(bpv, bph, out);
}

// round 7
// speedup vs baseline: 6.8374x; 1.0023x over previous
#include <cuda_runtime.h>
#include <cuda_fp16.h>
#include <cstdint>
#include <cstddef>

#define HEADS 8
#define NWIN  2048
#define MROWS (NWIN * 64)                   // 131072 token rows
#define BNC   ((size_t)MROWS * 256)         // 33,554,432 output elems per tensor

// ---------------- scratch (device globals; no allocation allowed) ----------
__device__ __half g_wt[2][1024 * 256];              // QKV weights, [src][col][k]
__device__ __half g_wpt[2][256 * 512];              // out-proj weights, [w][n][k]
__device__ __half g_qkv[(size_t)NWIN * 2 * 4 * HEADS * 64 * 32];  // head tiles
__device__ __half g_attv[(size_t)MROWS * 512];      // [cross_v | self_v]
__device__ __half g_atth[(size_t)MROWS * 512];      // [cross_h | self_h]
__device__ float  g_bias[4 * HEADS * 64 * 64];      // 512 KB

// ---------------- helpers ---------------------------------------------------
__device__ __forceinline__ uint32_t smem_u32(const void* p) {
    uint32_t a;
    asm("{ .reg .u64 t; cvta.to.shared.u64 t, %1; cvt.u32.u64 %0, t; }" : "=r"(a) : "l"(p));
    return a;
}
#define CP_ASYNC16(dst, src) \
    asm volatile("cp.async.cg.shared.global [%0], [%1], 16;" :: "r"(dst), "l"(src))
#define CP_COMMIT() asm volatile("cp.async.commit_group;" ::: "memory")

#define LDSM_X4(r, addr) \
    asm volatile("ldmatrix.sync.aligned.m8n8.x4.shared.b16 {%0,%1,%2,%3}, [%4];" \
        : "=r"((r)[0]), "=r"((r)[1]), "=r"((r)[2]), "=r"((r)[3]) : "r"(addr))

#define LDSM_X4_T(r, addr) \
    asm volatile("ldmatrix.sync.aligned.m8n8.x4.trans.shared.b16 {%0,%1,%2,%3}, [%4];" \
        : "=r"((r)[0]), "=r"((r)[1]), "=r"((r)[2]), "=r"((r)[3]) : "r"(addr))

#define MMA_16816(c, a, b0, b1) \
    asm volatile("mma.sync.aligned.m16n8k16.row.col.f32.f16.f16.f32 " \
        "{%0,%1,%2,%3}, {%4,%5,%6,%7}, {%8,%9}, {%0,%1,%2,%3};" \
        : "+f"((c)[0]), "+f"((c)[1]), "+f"((c)[2]), "+f"((c)[3]) \
        : "r"((a)[0]), "r"((a)[1]), "r"((a)[2]), "r"((a)[3]), "r"(b0), "r"(b1))

// split a float pair into fp16 high + fp16 low (residual) packs
__device__ __forceinline__ void pack_hl(float x, float y, uint32_t& hi, uint32_t& lo) {
    __half2 h = __floats2half2_rn(x, y);
    float2 r = __half22float2(h);
    __half2 l = __floats2half2_rn(x - r.x, y - r.y);
    hi = *(uint32_t*)&h;
    lo = *(uint32_t*)&l;
}

// ---------------- prep kernels ----------------------------------------------
__global__ void bias_kernel(const float* __restrict__ tcv, const float* __restrict__ tsv,
                            const float* __restrict__ tch, const float* __restrict__ tsh,
                            const int* __restrict__ rpi) {
    int idx = blockIdx.x * blockDim.x + threadIdx.x;   // 131072
    if (idx >= 4 * HEADS * 64 * 64) return;
    int m = idx & 63, n = (idx >> 6) & 63, h = (idx >> 12) & 7, a = idx >> 15;
    const float* tab = (a == 0) ? tcv : (a == 1) ? tsv : (a == 2) ? tch : tsh;
    g_bias[idx] = tab[rpi[n * 64 + m] * HEADS + h];
}

__global__ void wprep_kernel(const float* __restrict__ Ws, const float* __restrict__ We) {
    int idx = blockIdx.x * 256 + threadIdx.x;          // 524288
    int k = idx & 255, c = (idx >> 8) & 1023, src = idx >> 18;
    const float* W = src ? We : Ws;
    g_wt[src][c * 256 + k] = __float2half_rn(W[(size_t)k * 1024 + c]);
}
__global__ void wpprep_kernel(const float* __restrict__ Wpv, const float* __restrict__ Wph) {
    int idx = blockIdx.x * 256 + threadIdx.x;          // 262144
    int k = idx & 511, n = (idx >> 9) & 255, w = idx >> 17;
    const float* W = w ? Wph : Wpv;
    g_wpt[w][n * 512 + k] = __float2half_rn(W[(size_t)k * 256 + n]);
}

// ---------------- QKV projection GEMM (A-resident, 2 CTAs/SM) ----------------
// grid (1024 m-blocks, 2 src), 256 threads (8 warps = 4m x 2n of 32x32).
// smem/CTA: SA 128x256 fp16 (64 KB) + SB 64x256 fp16 (32 KB) + bias 4 KB = 100 KB.
// B double-buffering via register prefetch (8 x uint4 per thread).
#define SM_QKV (65536 + 32768 + 4096)

__global__ __launch_bounds__(256, 2)
void qkv_gemm(const float* __restrict__ input_x, const float* __restrict__ state_x,
              const float* __restrict__ bs, const float* __restrict__ be) {
    extern __shared__ __half smh[];
    __half* SA = smh;                            // 32768 halves
    __half* SB = smh + 32768;                    // 16384 halves
    float*  SBias = (float*)(smh + 32768 + 16384);   // 1024 floats

    const int tid = threadIdx.x, w = tid >> 5, lane = tid & 31;
    const int mb = blockIdx.x, src = blockIdx.y;
    const int wm = (w >> 1) * 32, wn = (w & 1) * 32;
    const int gid = lane >> 2, tig = lane & 3;

    // ---- prologue: A fp32 -> fp16 swizzled (128 rows x 256 k); bias -> smem --
    const float4* X4 = (const float4*)(src ? input_x : state_x);
    #pragma unroll
    for (int i = 0; i < 16; i++) {
        int ch = tid + i * 256;                  // 4096 chunks of 8 halves
        int r = ch >> 5, c = ch & 31;
        size_t gsrc = ((size_t)(mb * 128 + r) * 256 + c * 8) >> 2;
        float4 v0 = X4[gsrc], v1 = X4[gsrc + 1];
        __half2 h0 = __floats2half2_rn(v0.x, v0.y), h1 = __floats2half2_rn(v0.z, v0.w);
        __half2 h2 = __floats2half2_rn(v1.x, v1.y), h3 = __floats2half2_rn(v1.z, v1.w);
        uint4 u;
        u.x = *(uint32_t*)&h0; u.y = *(uint32_t*)&h1;
        u.z = *(uint32_t*)&h2; u.w = *(uint32_t*)&h3;
        *(uint4*)(SA + r * 256 + ((c ^ (r & 7)) << 3)) = u;
    }
    {
        const float* bv = src ? be : bs;
        #pragma unroll
        for (int i = 0; i < 4; i++) SBias[tid + i * 256] = bv[tid + i * 256];
    }

    const __half* Bsrc = g_wt[src];
    // register prefetch of B chunk nb=0 (2048 uint4 chunks, 8 per thread)
    uint4 breg[8];
    #pragma unroll
    for (int i = 0; i < 8; i++) {
        int ch = tid + i * 256;
        int r = ch >> 5, c = ch & 31;
        breg[i] = *(const uint4*)(Bsrc + (size_t)r * 256 + c * 8);
    }

    const float kscale = 0.17677669529663687f;
    const float m2 = src ? 1.0f : kscale;                // qsv / qev
    const float m3 = src ? kscale : kscale * kscale;     // qsh / qeh

    uint32_t baseA = smem_u32(SA);
    uint32_t baseB = smem_u32(SB);

    #pragma unroll 1
    for (int nb = 0; nb < 16; nb++) {
        __syncthreads();                         // SB readers of nb-1 done
        #pragma unroll
        for (int i = 0; i < 8; i++) {
            int ch = tid + i * 256;
            int r = ch >> 5, c = ch & 31;
            *(uint4*)(SB + r * 256 + ((c ^ (r & 7)) << 3)) = breg[i];
        }
        __syncthreads();                         // SB ready
        if (nb < 15) {                           // prefetch nb+1 (overlaps MMA)
            #pragma unroll
            for (int i = 0; i < 8; i++) {
                int ch = tid + i * 256;
                int r = ch >> 5, c = ch & 31;
                breg[i] = *(const uint4*)(Bsrc + (size_t)((nb + 1) * 64 + r) * 256 + c * 8);
            }
        }

        float acc[2][4][4];
        #pragma unroll
        for (int t = 0; t < 2; t++)
            #pragma unroll
            for (int j = 0; j < 4; j++)
                #pragma unroll
                for (int r = 0; r < 4; r++) acc[t][j][r] = 0.0f;

        #pragma unroll
        for (int ks = 0; ks < 16; ks++) {
            uint32_t af[2][4], bf[2][4];
            #pragma unroll
            for (int t = 0; t < 2; t++) {
                int row = wm + t * 16 + (lane & 15);
                int kc8 = ks * 2 + (lane >> 4);
                LDSM_X4(af[t], baseA + ((row * 256 + ((kc8 ^ (row & 7)) << 3)) << 1));
            }
            #pragma unroll
            for (int p = 0; p < 2; p++) {
                int n   = wn + p * 16 + ((lane >> 4) << 3) + (lane & 7);
                int kc8 = ks * 2 + ((lane >> 3) & 1);
                LDSM_X4(bf[p], baseB + ((n * 256 + ((kc8 ^ (n & 7)) << 3)) << 1));
            }
            #pragma unroll
            for (int t = 0; t < 2; t++)
                #pragma unroll
                for (int j = 0; j < 4; j++)
                    MMA_16816(acc[t][j], af[t],
                              bf[j >> 1][(j & 1) * 2], bf[j >> 1][(j & 1) * 2 + 1]);
        }

        // ---- epilogue: +bias (smem), q-scales, coalesced half2 stores ----
        #pragma unroll
        for (int t = 0; t < 2; t++)
            #pragma unroll
            for (int j = 0; j < 4; j++) {
                int nglob = nb * 64 + wn + j * 8 + tig * 2;   // 0..1023
                int f = nglob >> 8, h = (nglob >> 5) & 7, d = nglob & 31;
                float mult = (f == 2) ? m2 : (f == 3) ? m3 : 1.0f;
                float b0 = SBias[nglob], b1 = SBias[nglob + 1];
                #pragma unroll
                for (int rr = 0; rr < 2; rr++) {
                    int m = mb * 128 + wm + t * 16 + gid + rr * 8;
                    int b = m >> 6, ntok = m & 63;
                    size_t tile = ((((size_t)b * 2 + src) * 4 + f) * 8 + h) * 2048;
                    __half2 hv = __floats2half2_rn((acc[t][j][rr * 2] + b0) * mult,
                                                   (acc[t][j][rr * 2 + 1] + b1) * mult);
                    *(__half2*)(g_qkv + tile + ntok * 32 + d) = hv;
                }
            }
    }
}

// ---------------- attention kernel (HMMA flash-style) -----------------------
// CTA = 1 window, 8 warps = 4 attentions x 2 row-halves, loop 8 heads.
// All 8 tiles uniform [64 tok][32 d] layout; V loaded via ldmatrix.trans.
#define SM_ATT (2 * 8 * 2048 * 2)

__global__ __launch_bounds__(256, 2)
void attn_kernel() {
    extern __shared__ __half smh[];
    const int b = blockIdx.x, tid = threadIdx.x;
    const int w = tid >> 5, lane = tid & 31;
    const int gid = lane >> 2, tig = lane & 3;
    const int a = w >> 1, hf = w & 1;

    const int qt = (a == 0) ? 2 : (a == 1) ? 6 : (a == 2) ? 7 : 3;
    const int kt = (a == 0 || a == 3) ? 0 : 4;
    const int vt = kt + 1;
    __half* dst0 = (a <= 1) ? g_attv : g_atth;
    const int cbase = (a == 1 || a == 3) ? 256 : 0;

    auto stage = [&](int st, int h) {
        #pragma unroll
        for (int i = 0; i < 8; i++) {
            int ch = tid + i * 256;             // 2048 chunks of 16B
            int t = ch >> 8, c = ch & 255;
            const __half* src = g_qkv +
                ((((size_t)b * 2 + (t >> 2)) * 4 + (t & 3)) * 8 + h) * 2048 + c * 8;
            int r = c >> 2, c4 = c & 3;
            uint32_t off = r * 32 + ((c4 ^ ((r >> 1) & 3)) << 3);
            CP_ASYNC16(smem_u32(smh + (st * 8 + t) * 2048 + off), src);
        }
    };

    stage(0, 0);
    CP_COMMIT();

    #pragma unroll 1
    for (int h = 0; h < HEADS; h++) {
        int st = h & 1;
        if (h < 7) {
            stage(st ^ 1, h + 1);
            CP_COMMIT();
            asm volatile("cp.async.wait_group 1;" ::: "memory");
        } else {
            asm volatile("cp.async.wait_group 0;" ::: "memory");
        }
        __syncthreads();

        uint32_t Qb = smem_u32(smh + (st * 8 + qt) * 2048);
        uint32_t Kb = smem_u32(smh + (st * 8 + kt) * 2048);
        uint32_t Vb = smem_u32(smh + (st * 8 + vt) * 2048);
        const float* Bp = g_bias + (((a << 3) + h) << 12);

        #pragma unroll 1
        for (int mt = 0; mt < 2; mt++) {
            const int rbase = hf * 32 + mt * 16;
            const int r0 = rbase + gid;

            float sacc[8][4];
            #pragma unroll
            for (int nt = 0; nt < 8; nt++) {
                float2 t0 = *(const float2*)(Bp + r0 * 64 + nt * 8 + tig * 2);
                float2 t1 = *(const float2*)(Bp + (r0 + 8) * 64 + nt * 8 + tig * 2);
                sacc[nt][0] = t0.x; sacc[nt][1] = t0.y;
                sacc[nt][2] = t1.x; sacc[nt][3] = t1.y;
            }
            #pragma unroll
            for (int kk = 0; kk < 2; kk++) {
                uint32_t af[4];
                {
                    int row = rbase + (lane & 15);
                    int c4 = kk * 2 + (lane >> 4);
                    LDSM_X4(af, Qb + ((row * 32 + ((c4 ^ ((row >> 1) & 3)) << 3)) << 1));
                }
                #pragma unroll
                for (int ntp = 0; ntp < 4; ntp++) {
                    uint32_t bf[4];
                    int row = ntp * 16 + ((lane >> 4) << 3) + (lane & 7);
                    int c4 = kk * 2 + ((lane >> 3) & 1);
                    LDSM_X4(bf, Kb + ((row * 32 + ((c4 ^ ((row >> 1) & 3)) << 3)) << 1));
                    MMA_16816(sacc[ntp * 2],     af, bf[0], bf[1]);
                    MMA_16816(sacc[ntp * 2 + 1], af, bf[2], bf[3]);
                }
            }

            float mx0 = -1e30f, mx1 = -1e30f;
            #pragma unroll
            for (int nt = 0; nt < 8; nt++) {
                mx0 = fmaxf(mx0, fmaxf(sacc[nt][0], sacc[nt][1]));
                mx1 = fmaxf(mx1, fmaxf(sacc[nt][2], sacc[nt][3]));
            }
            mx0 = fmaxf(mx0, __shfl_xor_sync(0xffffffffu, mx0, 1));
            mx0 = fmaxf(mx0, __shfl_xor_sync(0xffffffffu, mx0, 2));
            mx1 = fmaxf(mx1, __shfl_xor_sync(0xffffffffu, mx1, 1));
            mx1 = fmaxf(mx1, __shfl_xor_sync(0xffffffffu, mx1, 2));
            const float L2E = 1.4426950408889634f;
            float sum0 = 0.0f, sum1 = 0.0f;
            #pragma unroll
            for (int nt = 0; nt < 8; nt++) {
                sacc[nt][0] = exp2f((sacc[nt][0] - mx0) * L2E);
                sacc[nt][1] = exp2f((sacc[nt][1] - mx0) * L2E);
                sacc[nt][2] = exp2f((sacc[nt][2] - mx1) * L2E);
                sacc[nt][3] = exp2f((sacc[nt][3] - mx1) * L2E);
                sum0 += sacc[nt][0] + sacc[nt][1];
                sum1 += sacc[nt][2] + sacc[nt][3];
            }
            sum0 += __shfl_xor_sync(0xffffffffu, sum0, 1);
            sum0 += __shfl_xor_sync(0xffffffffu, sum0, 2);
            sum1 += __shfl_xor_sync(0xffffffffu, sum1, 1);
            sum1 += __shfl_xor_sync(0xffffffffu, sum1, 2);
            float inv0 = __fdividef(1.0f, sum0);
            float inv1 = __fdividef(1.0f, sum1);

            uint32_t ph[8][2], pl[8][2];
            #pragma unroll
            for (int nt = 0; nt < 8; nt++) {
                pack_hl(sacc[nt][0], sacc[nt][1], ph[nt][0], pl[nt][0]);
                pack_hl(sacc[nt][2], sacc[nt][3], ph[nt][1], pl[nt][1]);
            }

            float oacc[4][4];
            #pragma unroll
            for (int n4 = 0; n4 < 4; n4++)
                #pragma unroll
                for (int r = 0; r < 4; r++) oacc[n4][r] = 0.0f;

            #pragma unroll
            for (int kk = 0; kk < 4; kk++) {
                uint32_t bf[2][4];
                #pragma unroll
                for (int ntp = 0; ntp < 2; ntp++) {
                    // trans-load of V[tok][d]: B-fragments for k=tok, n=d
                    int row = kk * 16 + ((lane >> 3) & 1) * 8 + (lane & 7);
                    int c4 = ntp * 2 + ((lane >> 4) & 1);
                    LDSM_X4_T(bf[ntp], Vb + ((row * 32 + ((c4 ^ ((row >> 1) & 3)) << 3)) << 1));
                }
                uint32_t ah[4] = { ph[2 * kk][0], ph[2 * kk][1],
                                   ph[2 * kk + 1][0], ph[2 * kk + 1][1] };
                uint32_t al[4] = { pl[2 * kk][0], pl[2 * kk][1],
                                   pl[2 * kk + 1][0], pl[2 * kk + 1][1] };
                #pragma unroll
                for (int n4 = 0; n4 < 4; n4++) {
                    MMA_16816(oacc[n4], ah, bf[n4 >> 1][(n4 & 1) * 2], bf[n4 >> 1][(n4 & 1) * 2 + 1]);
                    MMA_16816(oacc[n4], al, bf[n4 >> 1][(n4 & 1) * 2], bf[n4 >> 1][(n4 & 1) * 2 + 1]);
                }
            }

            size_t rowg = (size_t)b * 64 + r0;
            #pragma unroll
            for (int n4 = 0; n4 < 4; n4++) {
                int col = cbase + (h << 5) + n4 * 8 + tig * 2;
                __half2 v0 = __floats2half2_rn(oacc[n4][0] * inv0, oacc[n4][1] * inv0);
                __half2 v1 = __floats2half2_rn(oacc[n4][2] * inv1, oacc[n4][3] * inv1);
                *(__half2*)(dst0 + rowg * 512 + col)       = v0;
                *(__half2*)(dst0 + (rowg + 8) * 512 + col) = v1;
            }
        }
        __syncthreads();
    }
}

// ---------------- output projection GEMM (both tensors, grid.z) --------------
__global__ __launch_bounds__(256)
void out_gemm(const float* __restrict__ bpv, const float* __restrict__ bph,
              float* __restrict__ out) {
    __shared__ __align__(16) __half SA[2 * 128 * 64];
    __shared__ __align__(16) __half SB[2 * 64 * 64];
    const int mb = blockIdx.x, nb = blockIdx.y, which = blockIdx.z;
    const __half* A = which ? g_atth : g_attv;
    const __half* B = g_wpt[which];
    const float* bp = which ? bph : bpv;
    float* dst = out + (size_t)which * BNC;

    const int tid = threadIdx.x, w = tid >> 5, lane = tid & 31;
    const int wm = (w >> 1) * 32, wn = (w & 1) * 32;

    float acc[2][4][4];
    #pragma unroll
    for (int t = 0; t < 2; t++)
        #pragma unroll
        for (int j = 0; j < 4; j++)
            #pragma unroll
            for (int r = 0; r < 4; r++) acc[t][j][r] = 0.0f;

    auto issue = [&](int s, int kc) {
        __half* sa = SA + s * (128 * 64);
        __half* sb = SB + s * (64 * 64);
        #pragma unroll
        for (int i = 0; i < 4; i++) {
            int ch = tid + i * 256, r = ch >> 3, k8 = ch & 7;
            uint32_t d = smem_u32(sa + r * 64 + ((k8 ^ (r & 7)) << 3));
            CP_ASYNC16(d, A + (size_t)(mb * 128 + r) * 512 + kc * 64 + k8 * 8);
        }
        #pragma unroll
        for (int i = 0; i < 2; i++) {
            int ch = tid + i * 256, r = ch >> 3, k8 = ch & 7;
            uint32_t d = smem_u32(sb + r * 64 + ((k8 ^ (r & 7)) << 3));
            CP_ASYNC16(d, B + (size_t)(nb * 64 + r) * 512 + kc * 64 + k8 * 8);
        }
    };
    issue(0, 0);
    CP_COMMIT();

    #pragma unroll 1
    for (int kc = 0; kc < 8; kc++) {
        int s = kc & 1;
        if (kc + 1 < 8) {
            issue(s ^ 1, kc + 1);
            CP_COMMIT();
            asm volatile("cp.async.wait_group 1;" ::: "memory");
        } else {
            asm volatile("cp.async.wait_group 0;" ::: "memory");
        }
        __syncthreads();

        uint32_t baseA = smem_u32(SA + s * (128 * 64));
        uint32_t baseB = smem_u32(SB + s * (64 * 64));
        #pragma unroll
        for (int ks = 0; ks < 4; ks++) {
            uint32_t af[2][4], bf[2][4];
            #pragma unroll
            for (int t = 0; t < 2; t++) {
                int row = wm + t * 16 + (lane & 15);
                int kc8 = ks * 2 + (lane >> 4);
                LDSM_X4(af[t], baseA + ((row * 64 + ((kc8 ^ (row & 7)) << 3)) << 1));
            }
            #pragma unroll
            for (int p = 0; p < 2; p++) {
                int n   = wn + p * 16 + ((lane >> 4) << 3) + (lane & 7);
                int kc8 = ks * 2 + ((lane >> 3) & 1);
                LDSM_X4(bf[p], baseB + ((n * 64 + ((kc8 ^ (n & 7)) << 3)) << 1));
            }
            #pragma unroll
            for (int t = 0; t < 2; t++)
                #pragma unroll
                for (int j = 0; j < 4; j++)
                    MMA_16816(acc[t][j], af[t],
                              bf[j >> 1][(j & 1) * 2], bf[j >> 1][(j & 1) * 2 + 1]);
        }
        __syncthreads();
    }

    const int gid = lane >> 2, tig = lane & 3;
    #pragma unroll
    for (int t = 0; t < 2; t++)
        #pragma unroll
        for (int j = 0; j < 4; j++) {
            int n = nb * 64 + wn + j * 8 + tig * 2;       // 0..255
            float b0 = bp[n], b1 = bp[n + 1];
            #pragma unroll
            for (int rr = 0; rr < 2; rr++) {
                int m = mb * 128 + wm + t * 16 + gid + rr * 8;
                float2 v = make_float2(acc[t][j][rr * 2] + b0,
                                       acc[t][j][rr * 2 + 1] + b1);
                *(float2*)(dst + (size_t)m * 256 + n) = v;
            }
        }
}

// ---------------- launch -----------------------------------------------------
extern "C" void kernel_launch(void* const* d_in, const int* in_sizes, int n_in,
                              void* d_out, int out_size) {
    const float* input_x = (const float*)d_in[0];
    const float* state_x = (const float*)d_in[1];
    const float* Ws  = (const float*)d_in[2];
    const float* bs  = (const float*)d_in[3];
    const float* We  = (const float*)d_in[4];
    const float* be  = (const float*)d_in[5];
    const float* Wpv = (const float*)d_in[6];
    const float* bpv = (const float*)d_in[7];
    const float* Wph = (const float*)d_in[8];
    const float* bph = (const float*)d_in[9];
    const float* tcv = (const float*)d_in[10];
    const float* tsv = (const float*)d_in[11];
    const float* tch = (const float*)d_in[12];
    const float* tsh = (const float*)d_in[13];
    const int*   rpi = (const int*)d_in[14];
    float* out = (float*)d_out;

    cudaFuncSetAttribute(qkv_gemm, cudaFuncAttributeMaxDynamicSharedMemorySize, SM_QKV);
    cudaFuncSetAttribute(attn_kernel, cudaFuncAttributeMaxDynamicSharedMemorySize, SM_ATT);

    bias_kernel<<<512, 256>>>(tcv, tsv, tch, tsh, rpi);
    wprep_kernel<<<2048, 256>>>(Ws, We);
    wpprep_kernel<<<1024, 256>>>(Wpv, Wph);

    qkv_gemm<<<dim3(1024, 2), 256, SM_QKV>>>(input_x, state_x, bs, be);
    attn_kernel<<<NWIN, 256, SM_ATT>>>();
    out_gemm<<<dim3(1024, 4, 2), 256>>>(bpv, bph, out);
}